// round 1
// baseline (speedup 1.0000x reference)
#include <cuda_runtime.h>
#include <math.h>

#define T_TOK 2048
#define D_DIM 768
#define E_EXP 8
#define K_TOP 2
#define H_DIM 3072
#define NPAIR (T_TOK * K_TOP)

#define OUT_IDS  (T_TOK * D_DIM)
#define OUT_LOSS (T_TOK * D_DIM + T_TOK * K_TOP)

// ---------------- device scratch (static globals: allowed) ----------------
__device__ int   g_e[T_TOK][K_TOP];
__device__ float g_g[T_TOK][K_TOP];
__device__ int   g_count[E_EXP];
__device__ int   g_offset[E_EXP + 1];
__device__ int   g_cursor[E_EXP];
__device__ float g_smsum[E_EXP];
__device__ int   g_ltok[NPAIR];
__device__ float g_lgate[NPAIR];
__device__ float g_act[(size_t)NPAIR * H_DIM];   // ~50.3 MB activation scratch

// ---------------- zero per-call state ----------------
__global__ void zero_kernel() {
    int i = threadIdx.x;
    if (i < E_EXP) { g_count[i] = 0; g_smsum[i] = 0.0f; g_cursor[i] = 0; }
}

// ---------------- gating: logits, lb softmax, noisy top-2 ----------------
__global__ void gate_kernel(const float* __restrict__ x,
                            const float* __restrict__ noise,
                            const float* __restrict__ gw,
                            const float* __restrict__ nw,
                            float* __restrict__ out) {
    int t = blockIdx.x;
    int w = threadIdx.x >> 5;
    int lane = threadIdx.x & 31;
    __shared__ float logit[E_EXP];

    const float* xr = x + (size_t)t * D_DIM;
    float s = 0.0f;
    for (int d = lane; d < D_DIM; d += 32)
        s += xr[d] * gw[d * E_EXP + w];
    #pragma unroll
    for (int o = 16; o; o >>= 1) s += __shfl_xor_sync(0xffffffffu, s, o);
    if (lane == 0) logit[w] = s;
    __syncthreads();

    if (threadIdx.x == 0) {
        float l[E_EXP], ln[E_EXP];
        float m = -1e30f;
        #pragma unroll
        for (int e = 0; e < E_EXP; e++) { l[e] = logit[e]; m = fmaxf(m, l[e]); }
        float sum = 0.0f;
        float ex[E_EXP];
        #pragma unroll
        for (int e = 0; e < E_EXP; e++) { ex[e] = expf(l[e] - m); sum += ex[e]; }
        float inv = 1.0f / sum;
        #pragma unroll
        for (int e = 0; e < E_EXP; e++) atomicAdd(&g_smsum[e], ex[e] * inv);

        #pragma unroll
        for (int e = 0; e < E_EXP; e++) ln[e] = l[e] + noise[t * E_EXP + e] * nw[e];

        int b0 = 0;
        #pragma unroll
        for (int e = 1; e < E_EXP; e++) if (ln[e] > ln[b0]) b0 = e;  // strict: lowest idx wins ties
        int b1 = (b0 == 0) ? 1 : 0;
        #pragma unroll
        for (int e = 0; e < E_EXP; e++) if (e != b0 && ln[e] > ln[b1]) b1 = e;

        float v0 = ln[b0], v1 = ln[b1];
        float mm = fmaxf(v0, v1);
        float e0 = expf(v0 - mm), e1 = expf(v1 - mm);
        float denom = 1.0f / (e0 + e1);
        float g0 = e0 * denom, g1 = e1 * denom;

        g_e[t][0] = b0; g_e[t][1] = b1;
        g_g[t][0] = g0; g_g[t][1] = g1;
        atomicAdd(&g_count[b0], 1);
        atomicAdd(&g_count[b1], 1);
        out[OUT_IDS + t * K_TOP + 0] = (float)b0;
        out[OUT_IDS + t * K_TOP + 1] = (float)b1;
    }
}

// ---------------- prefix offsets + lb loss ----------------
__global__ void offsets_kernel(float* __restrict__ out) {
    if (threadIdx.x == 0) {
        int acc = 0;
        #pragma unroll
        for (int e = 0; e < E_EXP; e++) { g_offset[e] = acc; acc += g_count[e]; }
        g_offset[E_EXP] = acc;
        float loss = 0.0f;
        #pragma unroll
        for (int e = 0; e < E_EXP; e++) {
            float gm = g_smsum[e] / (float)T_TOK - 1.0f / (float)E_EXP;
            loss += gm * gm;
        }
        out[OUT_LOSS] = (loss / (float)E_EXP) * 0.01f;
    }
}

// ---------------- scatter tokens into compact per-expert lists ----------------
__global__ void scatter_kernel() {
    int t = blockIdx.x * blockDim.x + threadIdx.x;
    if (t >= T_TOK) return;
    #pragma unroll
    for (int k = 0; k < K_TOP; k++) {
        int e = g_e[t][k];
        int pos = atomicAdd(&g_cursor[e], 1);
        int r = g_offset[e] + pos;
        g_ltok[r] = t;
        g_lgate[r] = g_g[t][k];
    }
}

// ---------------- grouped GEMM 1: ACT = (x@w1+b1) * silu(x@w2+b2) ----------------
// tile M=64 (tokens), N=64 (h cols), K-step 16, fp32
__global__ __launch_bounds__(256) void gemm1_kernel(
        const float* __restrict__ x,
        const float* __restrict__ w1, const float* __restrict__ b1,
        const float* __restrict__ w2, const float* __restrict__ b2) {
    int e = blockIdx.z;
    int cnt = g_count[e];
    int m0 = blockIdx.x * 64;
    if (m0 >= cnt) return;
    int base = g_offset[e];
    int hb = blockIdx.y * 64;

    __shared__ float As[16][65];
    __shared__ float B1s[16][64];
    __shared__ float B2s[16][64];

    int tid = threadIdx.x;
    int tx = tid & 15, ty = tid >> 4;

    // A loader: row = tid/4 (0..63), 4 contiguous k per thread
    int lrow = tid >> 2;
    int lk   = (tid & 3) * 4;
    int tok  = g_ltok[base + min(m0 + lrow, cnt - 1)];
    const float* xrow = x + (size_t)tok * D_DIM;

    // B loader: brow = tid/16 (0..15), 4 contiguous cols
    int brow = tid >> 4, bc = (tid & 15) * 4;
    const float* w1p = w1 + ((size_t)e * D_DIM) * H_DIM + hb + bc;
    const float* w2p = w2 + ((size_t)e * D_DIM) * H_DIM + hb + bc;

    float ha[4][4] = {}, ga[4][4] = {};

    for (int k0 = 0; k0 < D_DIM; k0 += 16) {
        float4 av = *(const float4*)(xrow + k0 + lk);
        As[lk + 0][lrow] = av.x; As[lk + 1][lrow] = av.y;
        As[lk + 2][lrow] = av.z; As[lk + 3][lrow] = av.w;
        *(float4*)&B1s[brow][bc] = *(const float4*)(w1p + (size_t)(k0 + brow) * H_DIM);
        *(float4*)&B2s[brow][bc] = *(const float4*)(w2p + (size_t)(k0 + brow) * H_DIM);
        __syncthreads();
        #pragma unroll
        for (int kk = 0; kk < 16; kk++) {
            float a[4];
            #pragma unroll
            for (int i = 0; i < 4; i++) a[i] = As[kk][ty * 4 + i];
            float4 bb1 = *(const float4*)&B1s[kk][tx * 4];
            float4 bb2 = *(const float4*)&B2s[kk][tx * 4];
            #pragma unroll
            for (int i = 0; i < 4; i++) {
                ha[i][0] += a[i] * bb1.x; ha[i][1] += a[i] * bb1.y;
                ha[i][2] += a[i] * bb1.z; ha[i][3] += a[i] * bb1.w;
                ga[i][0] += a[i] * bb2.x; ga[i][1] += a[i] * bb2.y;
                ga[i][2] += a[i] * bb2.z; ga[i][3] += a[i] * bb2.w;
            }
        }
        __syncthreads();
    }

    const float* b1b = b1 + (size_t)e * H_DIM + hb;
    const float* b2b = b2 + (size_t)e * H_DIM + hb;
    #pragma unroll
    for (int i = 0; i < 4; i++) {
        int m = ty * 4 + i;
        if (m0 + m >= cnt) break;
        float* actp = g_act + (size_t)(base + m0 + m) * H_DIM + hb + tx * 4;
        float4 v;
        float vv[4];
        #pragma unroll
        for (int j = 0; j < 4; j++) {
            int c = tx * 4 + j;
            float hh = ha[i][j] + b1b[c];
            float gg = ga[i][j] + b2b[c];
            vv[j] = hh * (gg / (1.0f + expf(-gg)));   // h * silu(g)
        }
        v.x = vv[0]; v.y = vv[1]; v.z = vv[2]; v.w = vv[3];
        *(float4*)actp = v;
    }
}

// ---------------- grouped GEMM 2: out += gate * (ACT @ wp + bp) ----------------
__global__ __launch_bounds__(256) void gemm2_kernel(
        const float* __restrict__ wp, const float* __restrict__ bp,
        float* __restrict__ out) {
    int e = blockIdx.z;
    int cnt = g_count[e];
    int m0 = blockIdx.x * 64;
    if (m0 >= cnt) return;
    int base = g_offset[e];
    int db = blockIdx.y * 64;

    __shared__ float As[16][65];
    __shared__ float Bs[16][64];

    int tid = threadIdx.x;
    int tx = tid & 15, ty = tid >> 4;

    int lrow = tid >> 2;
    int lk   = (tid & 3) * 4;
    int gm   = min(m0 + lrow, cnt - 1);
    const float* arow = g_act + (size_t)(base + gm) * H_DIM;

    int brow = tid >> 4, bc = (tid & 15) * 4;
    const float* wpp = wp + (size_t)e * H_DIM * D_DIM + db + bc;

    float acc[4][4] = {};

    for (int k0 = 0; k0 < H_DIM; k0 += 16) {
        float4 av = *(const float4*)(arow + k0 + lk);
        As[lk + 0][lrow] = av.x; As[lk + 1][lrow] = av.y;
        As[lk + 2][lrow] = av.z; As[lk + 3][lrow] = av.w;
        *(float4*)&Bs[brow][bc] = *(const float4*)(wpp + (size_t)(k0 + brow) * D_DIM);
        __syncthreads();
        #pragma unroll
        for (int kk = 0; kk < 16; kk++) {
            float a[4];
            #pragma unroll
            for (int i = 0; i < 4; i++) a[i] = As[kk][ty * 4 + i];
            float4 bb = *(const float4*)&Bs[kk][tx * 4];
            #pragma unroll
            for (int i = 0; i < 4; i++) {
                acc[i][0] += a[i] * bb.x; acc[i][1] += a[i] * bb.y;
                acc[i][2] += a[i] * bb.z; acc[i][3] += a[i] * bb.w;
            }
        }
        __syncthreads();
    }

    const float* bpb = bp + (size_t)e * D_DIM + db;
    #pragma unroll
    for (int i = 0; i < 4; i++) {
        int m = ty * 4 + i;
        if (m0 + m >= cnt) break;
        int r = base + m0 + m;
        int t = g_ltok[r];
        float gt = g_lgate[r];
        float* orow = out + (size_t)t * D_DIM + db;
        #pragma unroll
        for (int j = 0; j < 4; j++) {
            int c = tx * 4 + j;
            atomicAdd(&orow[c], gt * (acc[i][j] + bpb[c]));
        }
    }
}

// ---------------- launch ----------------
extern "C" void kernel_launch(void* const* d_in, const int* in_sizes, int n_in,
                              void* d_out, int out_size) {
    const float* x     = (const float*)d_in[0];
    const float* noise = (const float*)d_in[1];
    const float* gw    = (const float*)d_in[2];
    const float* nw    = (const float*)d_in[3];
    const float* w1    = (const float*)d_in[4];
    const float* b1    = (const float*)d_in[5];
    const float* w2    = (const float*)d_in[6];
    const float* b2    = (const float*)d_in[7];
    const float* wp    = (const float*)d_in[8];
    const float* bp    = (const float*)d_in[9];
    float* out = (float*)d_out;

    cudaMemsetAsync(out, 0, (size_t)T_TOK * D_DIM * sizeof(float));
    zero_kernel<<<1, 32>>>();
    gate_kernel<<<T_TOK, 256>>>(x, noise, gw, nw, out);
    offsets_kernel<<<1, 32>>>(out);
    scatter_kernel<<<(T_TOK + 255) / 256, 256>>>();

    dim3 g1(T_TOK / 64, H_DIM / 64, E_EXP);   // (32, 48, 8); blocks past count[e] exit
    gemm1_kernel<<<g1, 256>>>(x, w1, b1, w2, b2);
    dim3 g2(T_TOK / 64, D_DIM / 64, E_EXP);   // (32, 12, 8)
    gemm2_kernel<<<g2, 256>>>(wp, bp, out);
}

// round 7
// speedup vs baseline: 2.0494x; 2.0494x over previous
#include <cuda_runtime.h>
#include <cuda_bf16.h>
#include <math.h>
#include <stdint.h>

#define T_TOK 2048
#define D_DIM 768
#define E_EXP 8
#define K_TOP 2
#define H_DIM 3072
#define NPAD  5120            // 4096 pairs + 8*127 padding headroom

#define OUT_IDS  (T_TOK * D_DIM)
#define OUT_LOSS (T_TOK * D_DIM + T_TOK * K_TOP)

typedef __nv_bfloat16 bf16;

// ---------------- device scratch ----------------
__device__ int   g_e[T_TOK][K_TOP];
__device__ float g_g[T_TOK][K_TOP];
__device__ int   g_rows[T_TOK][K_TOP];
__device__ int   g_count[E_EXP];
__device__ int   g_offset[E_EXP + 1];
__device__ int   g_cursor[E_EXP];
__device__ float g_smsum[E_EXP];
__device__ int   g_ltok[NPAD];

__device__ bf16  g_xgh[(size_t)NPAD * D_DIM];
__device__ bf16  g_xgl[(size_t)NPAD * D_DIM];
__device__ bf16  g_acth[(size_t)NPAD * H_DIM];
__device__ bf16  g_actl[(size_t)NPAD * H_DIM];
__device__ float g_y[(size_t)NPAD * D_DIM];

// ---------------- helpers ----------------
__device__ __forceinline__ uint32_t s2u(const void* p) {
    return (uint32_t)__cvta_generic_to_shared(p);
}

__device__ __forceinline__ void ldsm4(uint32_t* r, uint32_t addr) {
    asm volatile("ldmatrix.sync.aligned.m8n8.x4.shared.b16 {%0,%1,%2,%3}, [%4];"
        : "=r"(r[0]), "=r"(r[1]), "=r"(r[2]), "=r"(r[3]) : "r"(addr));
}
__device__ __forceinline__ void ldsm4t(uint32_t* r, uint32_t addr) {
    asm volatile("ldmatrix.sync.aligned.m8n8.x4.trans.shared.b16 {%0,%1,%2,%3}, [%4];"
        : "=r"(r[0]), "=r"(r[1]), "=r"(r[2]), "=r"(r[3]) : "r"(addr));
}
__device__ __forceinline__ void mma_bf16(float* c, const uint32_t* a, const uint32_t* b) {
    asm volatile(
        "mma.sync.aligned.m16n8k16.row.col.f32.bf16.bf16.f32 "
        "{%0,%1,%2,%3}, {%4,%5,%6,%7}, {%8,%9}, {%0,%1,%2,%3};"
        : "+f"(c[0]), "+f"(c[1]), "+f"(c[2]), "+f"(c[3])
        : "r"(a[0]), "r"(a[1]), "r"(a[2]), "r"(a[3]), "r"(b[0]), "r"(b[1]));
}

__device__ __forceinline__ uint32_t pk2(bf16 a, bf16 b) {
    return (uint32_t)__bfloat16_as_ushort(a) | ((uint32_t)__bfloat16_as_ushort(b) << 16);
}
__device__ __forceinline__ void split4(float4 v, uint2& uh, uint2& ul) {
    bf16 h0 = __float2bfloat16_rn(v.x), h1 = __float2bfloat16_rn(v.y);
    bf16 h2 = __float2bfloat16_rn(v.z), h3 = __float2bfloat16_rn(v.w);
    bf16 l0 = __float2bfloat16_rn(v.x - __bfloat162float(h0));
    bf16 l1 = __float2bfloat16_rn(v.y - __bfloat162float(h1));
    bf16 l2 = __float2bfloat16_rn(v.z - __bfloat162float(h2));
    bf16 l3 = __float2bfloat16_rn(v.w - __bfloat162float(h3));
    uh.x = pk2(h0, h1); uh.y = pk2(h2, h3);
    ul.x = pk2(l0, l1); ul.y = pk2(l2, l3);
}

// ---------------- init ----------------
__global__ void zero_kernel() {
    int i = blockIdx.x * blockDim.x + threadIdx.x;
    if (i < NPAD) g_ltok[i] = -1;
    if (i < E_EXP) { g_count[i] = 0; g_smsum[i] = 0.0f; g_cursor[i] = 0; }
}

// ---------------- gating ----------------
__global__ void gate_kernel(const float* __restrict__ x,
                            const float* __restrict__ noise,
                            const float* __restrict__ gw,
                            const float* __restrict__ nw,
                            float* __restrict__ out) {
    int t = blockIdx.x;
    int w = threadIdx.x >> 5;
    int lane = threadIdx.x & 31;
    __shared__ float logit[E_EXP];

    const float* xr = x + (size_t)t * D_DIM;
    float s = 0.0f;
    for (int d = lane; d < D_DIM; d += 32)
        s += xr[d] * gw[d * E_EXP + w];
    #pragma unroll
    for (int o = 16; o; o >>= 1) s += __shfl_xor_sync(0xffffffffu, s, o);
    if (lane == 0) logit[w] = s;
    __syncthreads();

    if (threadIdx.x == 0) {
        float l[E_EXP], ln[E_EXP];
        float m = -1e30f;
        #pragma unroll
        for (int e = 0; e < E_EXP; e++) { l[e] = logit[e]; m = fmaxf(m, l[e]); }
        float sum = 0.0f;
        float ex[E_EXP];
        #pragma unroll
        for (int e = 0; e < E_EXP; e++) { ex[e] = expf(l[e] - m); sum += ex[e]; }
        float inv = 1.0f / sum;
        #pragma unroll
        for (int e = 0; e < E_EXP; e++) atomicAdd(&g_smsum[e], ex[e] * inv);

        #pragma unroll
        for (int e = 0; e < E_EXP; e++) ln[e] = l[e] + noise[t * E_EXP + e] * nw[e];

        int b0 = 0;
        #pragma unroll
        for (int e = 1; e < E_EXP; e++) if (ln[e] > ln[b0]) b0 = e;
        int b1 = (b0 == 0) ? 1 : 0;
        #pragma unroll
        for (int e = 0; e < E_EXP; e++) if (e != b0 && ln[e] > ln[b1]) b1 = e;

        float v0 = ln[b0], v1 = ln[b1];
        float mm = fmaxf(v0, v1);
        float e0 = expf(v0 - mm), e1 = expf(v1 - mm);
        float denom = 1.0f / (e0 + e1);

        g_e[t][0] = b0; g_e[t][1] = b1;
        g_g[t][0] = e0 * denom; g_g[t][1] = e1 * denom;
        atomicAdd(&g_count[b0], 1);
        atomicAdd(&g_count[b1], 1);
        out[OUT_IDS + t * K_TOP + 0] = (float)b0;
        out[OUT_IDS + t * K_TOP + 1] = (float)b1;
    }
}

// ---------------- padded offsets + lb loss ----------------
__global__ void offsets_kernel(float* __restrict__ out) {
    if (threadIdx.x == 0) {
        int acc = 0;
        #pragma unroll
        for (int e = 0; e < E_EXP; e++) {
            g_offset[e] = acc;
            acc += (g_count[e] + 127) & ~127;
        }
        g_offset[E_EXP] = acc;
        float loss = 0.0f;
        #pragma unroll
        for (int e = 0; e < E_EXP; e++) {
            float gm = g_smsum[e] / (float)T_TOK - 1.0f / (float)E_EXP;
            loss += gm * gm;
        }
        out[OUT_LOSS] = (loss / (float)E_EXP) * 0.01f;
    }
}

// ---------------- scatter ----------------
__global__ void scatter_kernel() {
    int t = blockIdx.x * blockDim.x + threadIdx.x;
    if (t >= T_TOK) return;
    #pragma unroll
    for (int k = 0; k < K_TOP; k++) {
        int e = g_e[t][k];
        int pos = atomicAdd(&g_cursor[e], 1);
        int r = g_offset[e] + pos;
        g_ltok[r] = t;
        g_rows[t][k] = r;
    }
}

// ---------------- gather + bf16 hi/lo split of routed x rows ----------------
__global__ void gatherx_kernel(const float* __restrict__ x) {
    int r = blockIdx.x;
    int d = threadIdx.x * 4;
    int t = g_ltok[r];
    uint2 uh = make_uint2(0, 0), ul = make_uint2(0, 0);
    if (t >= 0) {
        float4 v = *(const float4*)(x + (size_t)t * D_DIM + d);
        split4(v, uh, ul);
    }
    *(uint2*)(g_xgh + (size_t)r * D_DIM + d) = uh;
    *(uint2*)(g_xgl + (size_t)r * D_DIM + d) = ul;
}

// ---------------- HMMA grouped GEMM 1: act = (x@w1+b1)*silu(x@w2+b2) ----------------
// block: 128 rows x 64 h-cols, both matrices; K=768, chunk 32, split-bf16 3-pass
__global__ __launch_bounds__(256) void gemm1_mma(
        const float* __restrict__ w1, const float* __restrict__ w2,
        const float* __restrict__ b1, const float* __restrict__ b2) {
    int e = blockIdx.z;
    int cnt = g_count[e];
    int m0 = blockIdx.x * 128;
    if (m0 >= cnt) return;
    int rbase = g_offset[e] + m0;
    int hb = blockIdx.y * 64;
    int tid = threadIdx.x;
    int lane = tid & 31, wid = tid >> 5;
    int wm = (wid & 3) * 32, wn = (wid >> 2) * 32;

    extern __shared__ char smraw[];
    bf16* smb = (bf16*)smraw;
    const int A_SZ = 128 * 40;   // stride 40 bf16 (80B) -> conflict-free ldmatrix
    const int B_SZ = 32 * 72;    // stride 72 bf16 (144B)
    const int STG  = 2 * A_SZ + 4 * B_SZ;

    const float* w1p = w1 + (size_t)e * D_DIM * H_DIM + hb;
    const float* w2p = w2 + (size_t)e * D_DIM * H_DIM + hb;
    const bf16* xh = g_xgh + (size_t)rbase * D_DIM;
    const bf16* xl = g_xgl + (size_t)rbase * D_DIM;

    float accH[2][4][4], accG[2][4][4];
    #pragma unroll
    for (int i = 0; i < 2; i++)
        #pragma unroll
        for (int j = 0; j < 4; j++)
            #pragma unroll
            for (int k = 0; k < 4; k++) { accH[i][j][k] = 0.f; accG[i][j][k] = 0.f; }

    int a_row = tid >> 2, a_part = tid & 3;
    int b_row = tid >> 4, b_seg = tid & 15;

    uint4 pAh[2], pAl[2];
    float4 pB1[2], pB2[2];

    #pragma unroll
    for (int it = 0; it < 2; it++) {
        pAh[it] = *(const uint4*)(xh + (size_t)(a_row + it * 64) * D_DIM + a_part * 8);
        pAl[it] = *(const uint4*)(xl + (size_t)(a_row + it * 64) * D_DIM + a_part * 8);
        pB1[it] = *(const float4*)(w1p + (size_t)(b_row + it * 16) * H_DIM + b_seg * 4);
        pB2[it] = *(const float4*)(w2p + (size_t)(b_row + it * 16) * H_DIM + b_seg * 4);
    }

    const int NK = D_DIM / 32;   // 24
    for (int kc = 0; kc < NK; kc++) {
        int p = kc & 1;
        bf16* sAh  = smb + p * STG;
        bf16* sAl  = sAh + A_SZ;
        bf16* sB1h = sAl + A_SZ;
        bf16* sB1l = sB1h + B_SZ;
        bf16* sB2h = sB1l + B_SZ;
        bf16* sB2l = sB2h + B_SZ;

        #pragma unroll
        for (int it = 0; it < 2; it++) {
            *(uint4*)(sAh + (a_row + it * 64) * 40 + a_part * 8) = pAh[it];
            *(uint4*)(sAl + (a_row + it * 64) * 40 + a_part * 8) = pAl[it];
            uint2 uh, ul;
            split4(pB1[it], uh, ul);
            *(uint2*)(sB1h + (b_row + it * 16) * 72 + b_seg * 4) = uh;
            *(uint2*)(sB1l + (b_row + it * 16) * 72 + b_seg * 4) = ul;
            split4(pB2[it], uh, ul);
            *(uint2*)(sB2h + (b_row + it * 16) * 72 + b_seg * 4) = uh;
            *(uint2*)(sB2l + (b_row + it * 16) * 72 + b_seg * 4) = ul;
        }
        __syncthreads();

        if (kc + 1 < NK) {
            int k0 = (kc + 1) * 32;
            #pragma unroll
            for (int it = 0; it < 2; it++) {
                pAh[it] = *(const uint4*)(xh + (size_t)(a_row + it * 64) * D_DIM + k0 + a_part * 8);
                pAl[it] = *(const uint4*)(xl + (size_t)(a_row + it * 64) * D_DIM + k0 + a_part * 8);
                pB1[it] = *(const float4*)(w1p + (size_t)(k0 + b_row + it * 16) * H_DIM + b_seg * 4);
                pB2[it] = *(const float4*)(w2p + (size_t)(k0 + b_row + it * 16) * H_DIM + b_seg * 4);
            }
        }

        #pragma unroll
        for (int k16 = 0; k16 < 32; k16 += 16) {
            uint32_t ah[2][4], al[2][4];
            #pragma unroll
            for (int mt = 0; mt < 2; mt++) {
                int ro = wm + mt * 16 + (lane & 15);
                int co = k16 + ((lane >> 4) << 3);
                ldsm4(ah[mt], s2u(sAh + ro * 40 + co));
                ldsm4(al[mt], s2u(sAl + ro * 40 + co));
            }
            #pragma unroll
            for (int q = 0; q < 2; q++) {
                int ro = k16 + (lane & 15);
                int co = wn + q * 16 + ((lane >> 4) << 3);
                uint32_t rh[4], rl[4];
                ldsm4t(rh, s2u(sB1h + ro * 72 + co));
                ldsm4t(rl, s2u(sB1l + ro * 72 + co));
                #pragma unroll
                for (int mt = 0; mt < 2; mt++)
                    #pragma unroll
                    for (int j = 0; j < 2; j++) {
                        mma_bf16(accH[mt][q * 2 + j], ah[mt], &rh[j * 2]);
                        mma_bf16(accH[mt][q * 2 + j], ah[mt], &rl[j * 2]);
                        mma_bf16(accH[mt][q * 2 + j], al[mt], &rh[j * 2]);
                    }
                ldsm4t(rh, s2u(sB2h + ro * 72 + co));
                ldsm4t(rl, s2u(sB2l + ro * 72 + co));
                #pragma unroll
                for (int mt = 0; mt < 2; mt++)
                    #pragma unroll
                    for (int j = 0; j < 2; j++) {
                        mma_bf16(accG[mt][q * 2 + j], ah[mt], &rh[j * 2]);
                        mma_bf16(accG[mt][q * 2 + j], ah[mt], &rl[j * 2]);
                        mma_bf16(accG[mt][q * 2 + j], al[mt], &rh[j * 2]);
                    }
            }
        }
        __syncthreads();
    }

    // epilogue: act = (h+b1)*silu(g+b2), stored bf16 hi/lo
    const float* b1p = b1 + (size_t)e * H_DIM + hb;
    const float* b2p = b2 + (size_t)e * H_DIM + hb;
    #pragma unroll
    for (int mt = 0; mt < 2; mt++) {
        int row0 = rbase + wm + mt * 16 + (lane >> 2);
        #pragma unroll
        for (int nt = 0; nt < 4; nt++) {
            int cl = wn + nt * 8 + (lane & 3) * 2;
            float bb1a = b1p[cl], bb1b = b1p[cl + 1];
            float bb2a = b2p[cl], bb2b = b2p[cl + 1];
            #pragma unroll
            for (int hf = 0; hf < 2; hf++) {
                float hv0 = accH[mt][nt][hf * 2 + 0] + bb1a;
                float hv1 = accH[mt][nt][hf * 2 + 1] + bb1b;
                float gv0 = accG[mt][nt][hf * 2 + 0] + bb2a;
                float gv1 = accG[mt][nt][hf * 2 + 1] + bb2b;
                float a0 = hv0 * (gv0 / (1.0f + expf(-gv0)));
                float a1 = hv1 * (gv1 / (1.0f + expf(-gv1)));
                bf16 h0 = __float2bfloat16_rn(a0), h1 = __float2bfloat16_rn(a1);
                uint32_t vh = pk2(h0, h1);
                uint32_t vl = pk2(__float2bfloat16_rn(a0 - __bfloat162float(h0)),
                                  __float2bfloat16_rn(a1 - __bfloat162float(h1)));
                size_t off = (size_t)(row0 + hf * 8) * H_DIM + hb + cl;
                *(uint32_t*)(g_acth + off) = vh;
                *(uint32_t*)(g_actl + off) = vl;
            }
        }
    }
}

// ---------------- HMMA grouped GEMM 2: y = act @ wp + bp ----------------
// block: 128 rows x 128 d-cols; K=3072, chunk 32
__global__ __launch_bounds__(256) void gemm2_mma(
        const float* __restrict__ wp, const float* __restrict__ bp) {
    int e = blockIdx.z;
    int cnt = g_count[e];
    int m0 = blockIdx.x * 128;
    if (m0 >= cnt) return;
    int rbase = g_offset[e] + m0;
    int db = blockIdx.y * 128;
    int tid = threadIdx.x;
    int lane = tid & 31, wid = tid >> 5;
    int wm = (wid & 3) * 32, wn = (wid >> 2) * 64;

    extern __shared__ char smraw[];
    bf16* smb = (bf16*)smraw;
    const int A_SZ = 128 * 40;
    const int B_SZ = 32 * 136;   // stride 136 bf16 (272B): 16B aligned, conflict-free
    const int STG  = 2 * A_SZ + 2 * B_SZ;

    const float* wpp = wp + (size_t)e * H_DIM * D_DIM + db;
    const bf16* ahp = g_acth + (size_t)rbase * H_DIM;
    const bf16* alp = g_actl + (size_t)rbase * H_DIM;

    float acc[2][8][4];
    #pragma unroll
    for (int i = 0; i < 2; i++)
        #pragma unroll
        for (int j = 0; j < 8; j++)
            #pragma unroll
            for (int k = 0; k < 4; k++) acc[i][j][k] = 0.f;

    int a_row = tid >> 2, a_part = tid & 3;
    int b_row = tid >> 5, b_seg = tid & 31;

    uint4 pAh[2], pAl[2];
    float4 pB[4];

    #pragma unroll
    for (int it = 0; it < 2; it++) {
        pAh[it] = *(const uint4*)(ahp + (size_t)(a_row + it * 64) * H_DIM + a_part * 8);
        pAl[it] = *(const uint4*)(alp + (size_t)(a_row + it * 64) * H_DIM + a_part * 8);
    }
    #pragma unroll
    for (int it = 0; it < 4; it++)
        pB[it] = *(const float4*)(wpp + (size_t)(b_row + it * 8) * D_DIM + b_seg * 4);

    const int NK = H_DIM / 32;   // 96
    for (int kc = 0; kc < NK; kc++) {
        int p = kc & 1;
        bf16* sAh = smb + p * STG;
        bf16* sAl = sAh + A_SZ;
        bf16* sBh = sAl + A_SZ;
        bf16* sBl = sBh + B_SZ;

        #pragma unroll
        for (int it = 0; it < 2; it++) {
            *(uint4*)(sAh + (a_row + it * 64) * 40 + a_part * 8) = pAh[it];
            *(uint4*)(sAl + (a_row + it * 64) * 40 + a_part * 8) = pAl[it];
        }
        #pragma unroll
        for (int it = 0; it < 4; it++) {
            uint2 uh, ul;
            split4(pB[it], uh, ul);
            *(uint2*)(sBh + (b_row + it * 8) * 136 + b_seg * 4) = uh;
            *(uint2*)(sBl + (b_row + it * 8) * 136 + b_seg * 4) = ul;
        }
        __syncthreads();

        if (kc + 1 < NK) {
            int k0 = (kc + 1) * 32;
            #pragma unroll
            for (int it = 0; it < 2; it++) {
                pAh[it] = *(const uint4*)(ahp + (size_t)(a_row + it * 64) * H_DIM + k0 + a_part * 8);
                pAl[it] = *(const uint4*)(alp + (size_t)(a_row + it * 64) * H_DIM + k0 + a_part * 8);
            }
            #pragma unroll
            for (int it = 0; it < 4; it++)
                pB[it] = *(const float4*)(wpp + (size_t)(k0 + b_row + it * 8) * D_DIM + b_seg * 4);
        }

        #pragma unroll
        for (int k16 = 0; k16 < 32; k16 += 16) {
            uint32_t ah[2][4], al[2][4];
            #pragma unroll
            for (int mt = 0; mt < 2; mt++) {
                int ro = wm + mt * 16 + (lane & 15);
                int co = k16 + ((lane >> 4) << 3);
                ldsm4(ah[mt], s2u(sAh + ro * 40 + co));
                ldsm4(al[mt], s2u(sAl + ro * 40 + co));
            }
            #pragma unroll
            for (int q = 0; q < 4; q++) {
                int ro = k16 + (lane & 15);
                int co = wn + q * 16 + ((lane >> 4) << 3);
                uint32_t rh[4], rl[4];
                ldsm4t(rh, s2u(sBh + ro * 136 + co));
                ldsm4t(rl, s2u(sBl + ro * 136 + co));
                #pragma unroll
                for (int mt = 0; mt < 2; mt++)
                    #pragma unroll
                    for (int j = 0; j < 2; j++) {
                        mma_bf16(acc[mt][q * 2 + j], ah[mt], &rh[j * 2]);
                        mma_bf16(acc[mt][q * 2 + j], ah[mt], &rl[j * 2]);
                        mma_bf16(acc[mt][q * 2 + j], al[mt], &rh[j * 2]);
                    }
            }
        }
        __syncthreads();
    }

    const float* bpp = bp + (size_t)e * D_DIM + db;
    #pragma unroll
    for (int mt = 0; mt < 2; mt++) {
        int row0 = rbase + wm + mt * 16 + (lane >> 2);
        #pragma unroll
        for (int nt = 0; nt < 8; nt++) {
            int cl = wn + nt * 8 + (lane & 3) * 2;
            float ba = bpp[cl], bb = bpp[cl + 1];
            #pragma unroll
            for (int hf = 0; hf < 2; hf++) {
                float2 v;
                v.x = acc[mt][nt][hf * 2 + 0] + ba;
                v.y = acc[mt][nt][hf * 2 + 1] + bb;
                *(float2*)(g_y + (size_t)(row0 + hf * 8) * D_DIM + db + cl) = v;
            }
        }
    }
}

// ---------------- final combine: out[t] = g0*y[r0] + g1*y[r1] ----------------
__global__ void combine_kernel(float* __restrict__ out) {
    int t = blockIdx.x;
    int d = threadIdx.x * 4;
    int r0 = g_rows[t][0], r1 = g_rows[t][1];
    float g0 = g_g[t][0], g1 = g_g[t][1];
    float4 a = *(const float4*)(g_y + (size_t)r0 * D_DIM + d);
    float4 b = *(const float4*)(g_y + (size_t)r1 * D_DIM + d);
    float4 o;
    o.x = g0 * a.x + g1 * b.x;
    o.y = g0 * a.y + g1 * b.y;
    o.z = g0 * a.z + g1 * b.z;
    o.w = g0 * a.w + g1 * b.w;
    *(float4*)(out + (size_t)t * D_DIM + d) = o;
}

// ---------------- launch ----------------
extern "C" void kernel_launch(void* const* d_in, const int* in_sizes, int n_in,
                              void* d_out, int out_size) {
    const float* x     = (const float*)d_in[0];
    const float* noise = (const float*)d_in[1];
    const float* gw    = (const float*)d_in[2];
    const float* nw    = (const float*)d_in[3];
    const float* w1    = (const float*)d_in[4];
    const float* b1    = (const float*)d_in[5];
    const float* w2    = (const float*)d_in[6];
    const float* b2    = (const float*)d_in[7];
    const float* wp    = (const float*)d_in[8];
    const float* bp    = (const float*)d_in[9];
    float* out = (float*)d_out;

    const int SM1 = 2 * (2 * 128 * 40 + 4 * 32 * 72) * 2;    // 77824 B
    const int SM2 = 2 * (2 * 128 * 40 + 2 * 32 * 136) * 2;   // 75776 B
    static int attr_done = 0;
    cudaFuncSetAttribute(gemm1_mma, cudaFuncAttributeMaxDynamicSharedMemorySize, SM1);
    cudaFuncSetAttribute(gemm2_mma, cudaFuncAttributeMaxDynamicSharedMemorySize, SM2);
    (void)attr_done;

    zero_kernel<<<(NPAD + 255) / 256, 256>>>();
    gate_kernel<<<T_TOK, 256>>>(x, noise, gw, nw, out);
    offsets_kernel<<<1, 32>>>(out);
    scatter_kernel<<<(T_TOK + 255) / 256, 256>>>();
    gatherx_kernel<<<NPAD, 192>>>(x);

    gemm1_mma<<<dim3(16, H_DIM / 64, E_EXP), 256, SM1>>>(w1, w2, b1, b2);
    gemm2_mma<<<dim3(16, D_DIM / 128, E_EXP), 256, SM2>>>(wp, bp);

    combine_kernel<<<T_TOK, 192>>>(out);
}

// round 9
// speedup vs baseline: 2.3475x; 1.1455x over previous
#include <cuda_runtime.h>
#include <cuda_bf16.h>
#include <math.h>
#include <stdint.h>

#define T_TOK 2048
#define D_DIM 768
#define E_EXP 8
#define K_TOP 2
#define H_DIM 3072
#define NPAD  5120            // 4096 pairs + 8*127 padding headroom

#define OUT_IDS  (T_TOK * D_DIM)
#define OUT_LOSS (T_TOK * D_DIM + T_TOK * K_TOP)

typedef __nv_bfloat16 bf16;

// ---------------- device scratch ----------------
__device__ int   g_e[T_TOK][K_TOP];
__device__ float g_g[T_TOK][K_TOP];
__device__ int   g_rows[T_TOK][K_TOP];
__device__ int   g_count[E_EXP];
__device__ int   g_offset[E_EXP + 1];
__device__ int   g_cursor[E_EXP];
__device__ float g_smsum[E_EXP];
__device__ int   g_ltok[NPAD];

__device__ bf16  g_xgh[(size_t)NPAD * D_DIM];
__device__ bf16  g_xgl[(size_t)NPAD * D_DIM];
__device__ bf16  g_w1h[(size_t)E_EXP * D_DIM * H_DIM];
__device__ bf16  g_w1l[(size_t)E_EXP * D_DIM * H_DIM];
__device__ bf16  g_w2h[(size_t)E_EXP * D_DIM * H_DIM];
__device__ bf16  g_w2l[(size_t)E_EXP * D_DIM * H_DIM];
__device__ bf16  g_wph[(size_t)E_EXP * H_DIM * D_DIM];
__device__ bf16  g_wpl[(size_t)E_EXP * H_DIM * D_DIM];
__device__ bf16  g_acth[(size_t)NPAD * H_DIM];
__device__ bf16  g_actl[(size_t)NPAD * H_DIM];
__device__ float g_y[(size_t)NPAD * D_DIM];

// ---------------- helpers ----------------
__device__ __forceinline__ uint32_t s2u(const void* p) {
    return (uint32_t)__cvta_generic_to_shared(p);
}
__device__ __forceinline__ void cp16(uint32_t dst, const void* src) {
    asm volatile("cp.async.ca.shared.global [%0], [%1], 16;" :: "r"(dst), "l"(src));
}
#define CP_COMMIT() asm volatile("cp.async.commit_group;")
#define CP_WAIT1()  asm volatile("cp.async.wait_group 1;")
#define CP_WAIT0()  asm volatile("cp.async.wait_group 0;")

__device__ __forceinline__ void ldsm4(uint32_t* r, uint32_t addr) {
    asm volatile("ldmatrix.sync.aligned.m8n8.x4.shared.b16 {%0,%1,%2,%3}, [%4];"
        : "=r"(r[0]), "=r"(r[1]), "=r"(r[2]), "=r"(r[3]) : "r"(addr));
}
__device__ __forceinline__ void ldsm4t(uint32_t* r, uint32_t addr) {
    asm volatile("ldmatrix.sync.aligned.m8n8.x4.trans.shared.b16 {%0,%1,%2,%3}, [%4];"
        : "=r"(r[0]), "=r"(r[1]), "=r"(r[2]), "=r"(r[3]) : "r"(addr));
}
__device__ __forceinline__ void mma_bf16(float* c, const uint32_t* a, const uint32_t* b) {
    asm volatile(
        "mma.sync.aligned.m16n8k16.row.col.f32.bf16.bf16.f32 "
        "{%0,%1,%2,%3}, {%4,%5,%6,%7}, {%8,%9}, {%0,%1,%2,%3};"
        : "+f"(c[0]), "+f"(c[1]), "+f"(c[2]), "+f"(c[3])
        : "r"(a[0]), "r"(a[1]), "r"(a[2]), "r"(a[3]), "r"(b[0]), "r"(b[1]));
}

__device__ __forceinline__ uint32_t pk2(bf16 a, bf16 b) {
    return (uint32_t)__bfloat16_as_ushort(a) | ((uint32_t)__bfloat16_as_ushort(b) << 16);
}
__device__ __forceinline__ void split4(float4 v, uint2& uh, uint2& ul) {
    bf16 h0 = __float2bfloat16_rn(v.x), h1 = __float2bfloat16_rn(v.y);
    bf16 h2 = __float2bfloat16_rn(v.z), h3 = __float2bfloat16_rn(v.w);
    bf16 l0 = __float2bfloat16_rn(v.x - __bfloat162float(h0));
    bf16 l1 = __float2bfloat16_rn(v.y - __bfloat162float(h1));
    bf16 l2 = __float2bfloat16_rn(v.z - __bfloat162float(h2));
    bf16 l3 = __float2bfloat16_rn(v.w - __bfloat162float(h3));
    uh.x = pk2(h0, h1); uh.y = pk2(h2, h3);
    ul.x = pk2(l0, l1); ul.y = pk2(l2, l3);
}

// ---------------- init ----------------
__global__ void zero_kernel() {
    int i = blockIdx.x * blockDim.x + threadIdx.x;
    if (i < NPAD) g_ltok[i] = -1;
    if (i < E_EXP) { g_count[i] = 0; g_smsum[i] = 0.0f; g_cursor[i] = 0; }
}

// ---------------- weight pre-split: fp32 -> bf16 hi/lo (same layout) ----------------
// which: 0 -> w1, 1 -> w2, 2 -> wp. Destinations are __device__ symbols referenced
// IN DEVICE CODE (host-side symbol addresses are invalid — that was the R8 bug).
__global__ void convW_kernel(const float4* __restrict__ src, int which, int n4) {
    int i = blockIdx.x * blockDim.x + threadIdx.x;
    if (i >= n4) return;
    uint2 uh, ul;
    split4(src[i], uh, ul);
    uint2* dh;
    uint2* dl;
    if (which == 0)      { dh = (uint2*)g_w1h; dl = (uint2*)g_w1l; }
    else if (which == 1) { dh = (uint2*)g_w2h; dl = (uint2*)g_w2l; }
    else                 { dh = (uint2*)g_wph; dl = (uint2*)g_wpl; }
    dh[i] = uh;
    dl[i] = ul;
}

// ---------------- gating ----------------
__global__ void gate_kernel(const float* __restrict__ x,
                            const float* __restrict__ noise,
                            const float* __restrict__ gw,
                            const float* __restrict__ nw,
                            float* __restrict__ out) {
    int t = blockIdx.x;
    int w = threadIdx.x >> 5;
    int lane = threadIdx.x & 31;
    __shared__ float logit[E_EXP];

    const float* xr = x + (size_t)t * D_DIM;
    float s = 0.0f;
    for (int d = lane; d < D_DIM; d += 32)
        s += xr[d] * gw[d * E_EXP + w];
    #pragma unroll
    for (int o = 16; o; o >>= 1) s += __shfl_xor_sync(0xffffffffu, s, o);
    if (lane == 0) logit[w] = s;
    __syncthreads();

    if (threadIdx.x == 0) {
        float l[E_EXP], ln[E_EXP];
        float m = -1e30f;
        #pragma unroll
        for (int e = 0; e < E_EXP; e++) { l[e] = logit[e]; m = fmaxf(m, l[e]); }
        float sum = 0.0f;
        float ex[E_EXP];
        #pragma unroll
        for (int e = 0; e < E_EXP; e++) { ex[e] = expf(l[e] - m); sum += ex[e]; }
        float inv = 1.0f / sum;
        #pragma unroll
        for (int e = 0; e < E_EXP; e++) atomicAdd(&g_smsum[e], ex[e] * inv);

        #pragma unroll
        for (int e = 0; e < E_EXP; e++) ln[e] = l[e] + noise[t * E_EXP + e] * nw[e];

        int b0 = 0;
        #pragma unroll
        for (int e = 1; e < E_EXP; e++) if (ln[e] > ln[b0]) b0 = e;
        int b1 = (b0 == 0) ? 1 : 0;
        #pragma unroll
        for (int e = 0; e < E_EXP; e++) if (e != b0 && ln[e] > ln[b1]) b1 = e;

        float v0 = ln[b0], v1 = ln[b1];
        float mm = fmaxf(v0, v1);
        float e0 = expf(v0 - mm), e1 = expf(v1 - mm);
        float denom = 1.0f / (e0 + e1);

        g_e[t][0] = b0; g_e[t][1] = b1;
        g_g[t][0] = e0 * denom; g_g[t][1] = e1 * denom;
        atomicAdd(&g_count[b0], 1);
        atomicAdd(&g_count[b1], 1);
        out[OUT_IDS + t * K_TOP + 0] = (float)b0;
        out[OUT_IDS + t * K_TOP + 1] = (float)b1;
    }
}

// ---------------- padded offsets + lb loss ----------------
__global__ void offsets_kernel(float* __restrict__ out) {
    if (threadIdx.x == 0) {
        int acc = 0;
        #pragma unroll
        for (int e = 0; e < E_EXP; e++) {
            g_offset[e] = acc;
            acc += (g_count[e] + 127) & ~127;
        }
        g_offset[E_EXP] = acc;
        float loss = 0.0f;
        #pragma unroll
        for (int e = 0; e < E_EXP; e++) {
            float gm = g_smsum[e] / (float)T_TOK - 1.0f / (float)E_EXP;
            loss += gm * gm;
        }
        out[OUT_LOSS] = (loss / (float)E_EXP) * 0.01f;
    }
}

// ---------------- scatter ----------------
__global__ void scatter_kernel() {
    int t = blockIdx.x * blockDim.x + threadIdx.x;
    if (t >= T_TOK) return;
    #pragma unroll
    for (int k = 0; k < K_TOP; k++) {
        int e = g_e[t][k];
        int pos = atomicAdd(&g_cursor[e], 1);
        int r = g_offset[e] + pos;
        g_ltok[r] = t;
        g_rows[t][k] = r;
    }
}

// ---------------- gather + bf16 hi/lo split of routed x rows ----------------
__global__ void gatherx_kernel(const float* __restrict__ x) {
    int r = blockIdx.x;
    int d = threadIdx.x * 4;
    int t = g_ltok[r];
    uint2 uh = make_uint2(0, 0), ul = make_uint2(0, 0);
    if (t >= 0) {
        float4 v = *(const float4*)(x + (size_t)t * D_DIM + d);
        split4(v, uh, ul);
    }
    *(uint2*)(g_xgh + (size_t)r * D_DIM + d) = uh;
    *(uint2*)(g_xgl + (size_t)r * D_DIM + d) = ul;
}

// ---------------- HMMA grouped GEMM 1: act = (x@w1+b1)*silu(x@w2+b2) ----------------
// block: 128 rows x 64 h-cols (both matrices); K=768, chunk 32, cp.async double buffer
__global__ __launch_bounds__(256) void gemm1_mma(
        const float* __restrict__ b1, const float* __restrict__ b2) {
    int e = blockIdx.z;
    int cnt = g_count[e];
    int m0 = blockIdx.x * 128;
    if (m0 >= cnt) return;
    int rbase = g_offset[e] + m0;
    int hb = blockIdx.y * 64;
    int tid = threadIdx.x;
    int lane = tid & 31, wid = tid >> 5;
    int wm = (wid & 3) * 32, wn = (wid >> 2) * 32;

    extern __shared__ char smraw[];
    bf16* smb = (bf16*)smraw;
    const int A_SZ = 128 * 40;   // elts; stride 40 (80B) -> conflict-free ldmatrix
    const int B_SZ = 32 * 72;    // elts; stride 72 (144B)
    const int STG  = 2 * A_SZ + 4 * B_SZ;        // elts per stage
    const uint32_t STGB = (uint32_t)STG * 2;     // bytes per stage

    // loader lanes
    int a_row = tid >> 1, a_half = tid & 1;      // A: 128 rows, 2 thr/row, 2x16B each
    int b_row = tid >> 3, b_col = (tid & 7) * 8; // B: 32 rows, 8 thr/row, 1x16B per mat

    const bf16* xh_p  = g_xgh + (size_t)(rbase + a_row) * D_DIM + a_half * 16;
    const bf16* xl_p  = g_xgl + (size_t)(rbase + a_row) * D_DIM + a_half * 16;
    const bf16* w1h_p = g_w1h + (size_t)e * D_DIM * H_DIM + hb + b_col;
    const bf16* w1l_p = g_w1l + (size_t)e * D_DIM * H_DIM + hb + b_col;
    const bf16* w2h_p = g_w2h + (size_t)e * D_DIM * H_DIM + hb + b_col;
    const bf16* w2l_p = g_w2l + (size_t)e * D_DIM * H_DIM + hb + b_col;

    uint32_t smbase = s2u(smb);
    uint32_t dAh  = smbase + (uint32_t)(a_row * 40 + a_half * 16) * 2;
    uint32_t dAl  = dAh + A_SZ * 2;
    uint32_t dB1h = smbase + (uint32_t)(2 * A_SZ + b_row * 72 + b_col) * 2;
    uint32_t dB1l = dB1h + B_SZ * 2;
    uint32_t dB2h = dB1l + B_SZ * 2;
    uint32_t dB2l = dB2h + B_SZ * 2;

    float accH[2][4][4], accG[2][4][4];
    #pragma unroll
    for (int i = 0; i < 2; i++)
        #pragma unroll
        for (int j = 0; j < 4; j++)
            #pragma unroll
            for (int k = 0; k < 4; k++) { accH[i][j][k] = 0.f; accG[i][j][k] = 0.f; }

    const int NK = D_DIM / 32;   // 24

    // prologue: stage 0
    {
        cp16(dAh, xh_p);  cp16(dAh + 16, xh_p + 8);
        cp16(dAl, xl_p);  cp16(dAl + 16, xl_p + 8);
        size_t rk = (size_t)b_row * H_DIM;
        cp16(dB1h, w1h_p + rk); cp16(dB1l, w1l_p + rk);
        cp16(dB2h, w2h_p + rk); cp16(dB2l, w2l_p + rk);
        CP_COMMIT();
    }

    for (int kc = 0; kc < NK; kc++) {
        int p = kc & 1;
        if (kc + 1 < NK) {
            int k0 = (kc + 1) * 32;
            uint32_t so = (uint32_t)((kc + 1) & 1) * STGB;
            cp16(dAh + so, xh_p + k0);  cp16(dAh + so + 16, xh_p + k0 + 8);
            cp16(dAl + so, xl_p + k0);  cp16(dAl + so + 16, xl_p + k0 + 8);
            size_t rk = (size_t)(k0 + b_row) * H_DIM;
            cp16(dB1h + so, w1h_p + rk); cp16(dB1l + so, w1l_p + rk);
            cp16(dB2h + so, w2h_p + rk); cp16(dB2l + so, w2l_p + rk);
            CP_COMMIT();
            CP_WAIT1();
        } else {
            CP_WAIT0();
        }
        __syncthreads();

        bf16* sAh  = smb + p * STG;
        bf16* sAl  = sAh + A_SZ;
        bf16* sB1h = sAl + A_SZ;
        bf16* sB1l = sB1h + B_SZ;
        bf16* sB2h = sB1l + B_SZ;
        bf16* sB2l = sB2h + B_SZ;

        #pragma unroll
        for (int k16 = 0; k16 < 32; k16 += 16) {
            uint32_t ah[2][4], al[2][4];
            #pragma unroll
            for (int mt = 0; mt < 2; mt++) {
                int ro = wm + mt * 16 + (lane & 15);
                int co = k16 + ((lane >> 4) << 3);
                ldsm4(ah[mt], s2u(sAh + ro * 40 + co));
                ldsm4(al[mt], s2u(sAl + ro * 40 + co));
            }
            #pragma unroll
            for (int q = 0; q < 2; q++) {
                int ro = k16 + (lane & 15);
                int co = wn + q * 16 + ((lane >> 4) << 3);
                uint32_t rh[4], rl[4];
                ldsm4t(rh, s2u(sB1h + ro * 72 + co));
                ldsm4t(rl, s2u(sB1l + ro * 72 + co));
                #pragma unroll
                for (int mt = 0; mt < 2; mt++)
                    #pragma unroll
                    for (int j = 0; j < 2; j++) {
                        mma_bf16(accH[mt][q * 2 + j], ah[mt], &rh[j * 2]);
                        mma_bf16(accH[mt][q * 2 + j], ah[mt], &rl[j * 2]);
                        mma_bf16(accH[mt][q * 2 + j], al[mt], &rh[j * 2]);
                    }
                ldsm4t(rh, s2u(sB2h + ro * 72 + co));
                ldsm4t(rl, s2u(sB2l + ro * 72 + co));
                #pragma unroll
                for (int mt = 0; mt < 2; mt++)
                    #pragma unroll
                    for (int j = 0; j < 2; j++) {
                        mma_bf16(accG[mt][q * 2 + j], ah[mt], &rh[j * 2]);
                        mma_bf16(accG[mt][q * 2 + j], ah[mt], &rl[j * 2]);
                        mma_bf16(accG[mt][q * 2 + j], al[mt], &rh[j * 2]);
                    }
            }
        }
        __syncthreads();
    }

    // epilogue: act = (h+b1)*silu(g+b2), stored bf16 hi/lo
    const float* b1p = b1 + (size_t)e * H_DIM + hb;
    const float* b2p = b2 + (size_t)e * H_DIM + hb;
    #pragma unroll
    for (int mt = 0; mt < 2; mt++) {
        int row0 = rbase + wm + mt * 16 + (lane >> 2);
        #pragma unroll
        for (int nt = 0; nt < 4; nt++) {
            int cl = wn + nt * 8 + (lane & 3) * 2;
            float bb1a = b1p[cl], bb1b = b1p[cl + 1];
            float bb2a = b2p[cl], bb2b = b2p[cl + 1];
            #pragma unroll
            for (int hf = 0; hf < 2; hf++) {
                float hv0 = accH[mt][nt][hf * 2 + 0] + bb1a;
                float hv1 = accH[mt][nt][hf * 2 + 1] + bb1b;
                float gv0 = accG[mt][nt][hf * 2 + 0] + bb2a;
                float gv1 = accG[mt][nt][hf * 2 + 1] + bb2b;
                float a0 = hv0 * (gv0 / (1.0f + expf(-gv0)));
                float a1 = hv1 * (gv1 / (1.0f + expf(-gv1)));
                bf16 h0 = __float2bfloat16_rn(a0), h1 = __float2bfloat16_rn(a1);
                uint32_t vh = pk2(h0, h1);
                uint32_t vl = pk2(__float2bfloat16_rn(a0 - __bfloat162float(h0)),
                                  __float2bfloat16_rn(a1 - __bfloat162float(h1)));
                size_t off = (size_t)(row0 + hf * 8) * H_DIM + hb + cl;
                *(uint32_t*)(g_acth + off) = vh;
                *(uint32_t*)(g_actl + off) = vl;
            }
        }
    }
}

// ---------------- HMMA grouped GEMM 2: y = act @ wp + bp ----------------
// block: 128 rows x 128 d-cols; K=3072, chunk 32, cp.async double buffer
__global__ __launch_bounds__(256) void gemm2_mma(const float* __restrict__ bp) {
    int e = blockIdx.z;
    int cnt = g_count[e];
    int m0 = blockIdx.x * 128;
    if (m0 >= cnt) return;
    int rbase = g_offset[e] + m0;
    int db = blockIdx.y * 128;
    int tid = threadIdx.x;
    int lane = tid & 31, wid = tid >> 5;
    int wm = (wid & 3) * 32, wn = (wid >> 2) * 64;

    extern __shared__ char smraw[];
    bf16* smb = (bf16*)smraw;
    const int A_SZ = 128 * 40;
    const int B_SZ = 32 * 136;   // stride 136 (272B)
    const int STG  = 2 * A_SZ + 2 * B_SZ;
    const uint32_t STGB = (uint32_t)STG * 2;

    int a_row = tid >> 1, a_half = tid & 1;
    int b_row = tid >> 3, b_col = (tid & 7) * 8;   // spans at b_col and b_col+64

    const bf16* ah_p = g_acth + (size_t)(rbase + a_row) * H_DIM + a_half * 16;
    const bf16* al_p = g_actl + (size_t)(rbase + a_row) * H_DIM + a_half * 16;
    const bf16* wh_p = g_wph + (size_t)e * H_DIM * D_DIM + db + b_col;
    const bf16* wl_p = g_wpl + (size_t)e * H_DIM * D_DIM + db + b_col;

    uint32_t smbase = s2u(smb);
    uint32_t dAh = smbase + (uint32_t)(a_row * 40 + a_half * 16) * 2;
    uint32_t dAl = dAh + A_SZ * 2;
    uint32_t dBh = smbase + (uint32_t)(2 * A_SZ + b_row * 136 + b_col) * 2;
    uint32_t dBl = dBh + B_SZ * 2;

    float acc[2][8][4];
    #pragma unroll
    for (int i = 0; i < 2; i++)
        #pragma unroll
        for (int j = 0; j < 8; j++)
            #pragma unroll
            for (int k = 0; k < 4; k++) acc[i][j][k] = 0.f;

    const int NK = H_DIM / 32;   // 96

    {
        cp16(dAh, ah_p);  cp16(dAh + 16, ah_p + 8);
        cp16(dAl, al_p);  cp16(dAl + 16, al_p + 8);
        size_t rk = (size_t)b_row * D_DIM;
        cp16(dBh, wh_p + rk);       cp16(dBh + 128, wh_p + rk + 64);
        cp16(dBl, wl_p + rk);       cp16(dBl + 128, wl_p + rk + 64);
        CP_COMMIT();
    }

    for (int kc = 0; kc < NK; kc++) {
        int p = kc & 1;
        if (kc + 1 < NK) {
            int k0 = (kc + 1) * 32;
            uint32_t so = (uint32_t)((kc + 1) & 1) * STGB;
            cp16(dAh + so, ah_p + k0);  cp16(dAh + so + 16, ah_p + k0 + 8);
            cp16(dAl + so, al_p + k0);  cp16(dAl + so + 16, al_p + k0 + 8);
            size_t rk = (size_t)(k0 + b_row) * D_DIM;
            cp16(dBh + so, wh_p + rk);       cp16(dBh + so + 128, wh_p + rk + 64);
            cp16(dBl + so, wl_p + rk);       cp16(dBl + so + 128, wl_p + rk + 64);
            CP_COMMIT();
            CP_WAIT1();
        } else {
            CP_WAIT0();
        }
        __syncthreads();

        bf16* sAh = smb + p * STG;
        bf16* sAl = sAh + A_SZ;
        bf16* sBh = sAl + A_SZ;
        bf16* sBl = sBh + B_SZ;

        #pragma unroll
        for (int k16 = 0; k16 < 32; k16 += 16) {
            uint32_t ah[2][4], al[2][4];
            #pragma unroll
            for (int mt = 0; mt < 2; mt++) {
                int ro = wm + mt * 16 + (lane & 15);
                int co = k16 + ((lane >> 4) << 3);
                ldsm4(ah[mt], s2u(sAh + ro * 40 + co));
                ldsm4(al[mt], s2u(sAl + ro * 40 + co));
            }
            #pragma unroll
            for (int q = 0; q < 4; q++) {
                int ro = k16 + (lane & 15);
                int co = wn + q * 16 + ((lane >> 4) << 3);
                uint32_t rh[4], rl[4];
                ldsm4t(rh, s2u(sBh + ro * 136 + co));
                ldsm4t(rl, s2u(sBl + ro * 136 + co));
                #pragma unroll
                for (int mt = 0; mt < 2; mt++)
                    #pragma unroll
                    for (int j = 0; j < 2; j++) {
                        mma_bf16(acc[mt][q * 2 + j], ah[mt], &rh[j * 2]);
                        mma_bf16(acc[mt][q * 2 + j], ah[mt], &rl[j * 2]);
                        mma_bf16(acc[mt][q * 2 + j], al[mt], &rh[j * 2]);
                    }
            }
        }
        __syncthreads();
    }

    const float* bpp = bp + (size_t)e * D_DIM + db;
    #pragma unroll
    for (int mt = 0; mt < 2; mt++) {
        int row0 = rbase + wm + mt * 16 + (lane >> 2);
        #pragma unroll
        for (int nt = 0; nt < 8; nt++) {
            int cl = wn + nt * 8 + (lane & 3) * 2;
            float ba = bpp[cl], bb = bpp[cl + 1];
            #pragma unroll
            for (int hf = 0; hf < 2; hf++) {
                float2 v;
                v.x = acc[mt][nt][hf * 2 + 0] + ba;
                v.y = acc[mt][nt][hf * 2 + 1] + bb;
                *(float2*)(g_y + (size_t)(row0 + hf * 8) * D_DIM + db + cl) = v;
            }
        }
    }
}

// ---------------- final combine: out[t] = g0*y[r0] + g1*y[r1] ----------------
__global__ void combine_kernel(float* __restrict__ out) {
    int t = blockIdx.x;
    int d = threadIdx.x * 4;
    int r0 = g_rows[t][0], r1 = g_rows[t][1];
    float g0 = g_g[t][0], g1 = g_g[t][1];
    float4 a = *(const float4*)(g_y + (size_t)r0 * D_DIM + d);
    float4 b = *(const float4*)(g_y + (size_t)r1 * D_DIM + d);
    float4 o;
    o.x = g0 * a.x + g1 * b.x;
    o.y = g0 * a.y + g1 * b.y;
    o.z = g0 * a.z + g1 * b.z;
    o.w = g0 * a.w + g1 * b.w;
    *(float4*)(out + (size_t)t * D_DIM + d) = o;
}

// ---------------- launch ----------------
extern "C" void kernel_launch(void* const* d_in, const int* in_sizes, int n_in,
                              void* d_out, int out_size) {
    const float* x     = (const float*)d_in[0];
    const float* noise = (const float*)d_in[1];
    const float* gw    = (const float*)d_in[2];
    const float* nw    = (const float*)d_in[3];
    const float* w1    = (const float*)d_in[4];
    const float* b1    = (const float*)d_in[5];
    const float* w2    = (const float*)d_in[6];
    const float* b2    = (const float*)d_in[7];
    const float* wp    = (const float*)d_in[8];
    const float* bp    = (const float*)d_in[9];
    float* out = (float*)d_out;

    const int SM1 = 2 * (2 * 128 * 40 + 4 * 32 * 72) * 2;    // 77824 B
    const int SM2 = 2 * (2 * 128 * 40 + 2 * 32 * 136) * 2;   // 75776 B
    cudaFuncSetAttribute(gemm1_mma, cudaFuncAttributeMaxDynamicSharedMemorySize, SM1);
    cudaFuncSetAttribute(gemm2_mma, cudaFuncAttributeMaxDynamicSharedMemorySize, SM2);

    const int NW4 = E_EXP * D_DIM * H_DIM / 4;   // 4718592 float4s per weight tensor
    convW_kernel<<<(NW4 + 255) / 256, 256>>>((const float4*)w1, 0, NW4);
    convW_kernel<<<(NW4 + 255) / 256, 256>>>((const float4*)w2, 1, NW4);
    convW_kernel<<<(NW4 + 255) / 256, 256>>>((const float4*)wp, 2, NW4);

    zero_kernel<<<(NPAD + 255) / 256, 256>>>();
    gate_kernel<<<T_TOK, 256>>>(x, noise, gw, nw, out);
    offsets_kernel<<<1, 32>>>(out);
    scatter_kernel<<<(T_TOK + 255) / 256, 256>>>();
    gatherx_kernel<<<NPAD, 192>>>(x);

    gemm1_mma<<<dim3(16, H_DIM / 64, E_EXP), 256, SM1>>>(b1, b2);
    gemm2_mma<<<dim3(16, D_DIM / 128, E_EXP), 256, SM2>>>(bp);

    combine_kernel<<<T_TOK, 192>>>(out);
}

// round 11
// speedup vs baseline: 3.2613x; 1.3892x over previous
#include <cuda_runtime.h>
#include <cuda_fp16.h>
#include <math.h>
#include <stdint.h>

#define T_TOK 2048
#define D_DIM 768
#define E_EXP 8
#define K_TOP 2
#define H_DIM 3072
#define NPAD  5120

#define OUT_IDS  (T_TOK * D_DIM)
#define OUT_LOSS (T_TOK * D_DIM + T_TOK * K_TOP)

// ---------------- device scratch ----------------
__device__ int   g_e[T_TOK][K_TOP];
__device__ float g_g[T_TOK][K_TOP];
__device__ int   g_rows[T_TOK][K_TOP];
__device__ int   g_count[E_EXP];
__device__ int   g_offset[E_EXP + 1];
__device__ int   g_cursor[E_EXP];
__device__ float g_smsum[E_EXP];
__device__ int   g_ltok[NPAD];

__device__ __half g_xgh[(size_t)NPAD * D_DIM];
__device__ __half g_xgl[(size_t)NPAD * D_DIM];
__device__ __half g_w1h[(size_t)E_EXP * D_DIM * H_DIM];
__device__ __half g_w2h[(size_t)E_EXP * D_DIM * H_DIM];
__device__ __half g_wph[(size_t)E_EXP * H_DIM * D_DIM];
__device__ __half g_acth[(size_t)NPAD * H_DIM];
__device__ __half g_actl[(size_t)NPAD * H_DIM];
__device__ float g_y[(size_t)NPAD * D_DIM];

// ---------------- helpers ----------------
__device__ __forceinline__ uint32_t s2u(const void* p) {
    return (uint32_t)__cvta_generic_to_shared(p);
}
__device__ __forceinline__ void cp16(uint32_t dst, const void* src) {
    asm volatile("cp.async.ca.shared.global [%0], [%1], 16;" :: "r"(dst), "l"(src));
}
#define CP_COMMIT() asm volatile("cp.async.commit_group;")
#define CP_WAIT1()  asm volatile("cp.async.wait_group 1;")
#define CP_WAIT0()  asm volatile("cp.async.wait_group 0;")

__device__ __forceinline__ void ldsm4(uint32_t* r, uint32_t addr) {
    asm volatile("ldmatrix.sync.aligned.m8n8.x4.shared.b16 {%0,%1,%2,%3}, [%4];"
        : "=r"(r[0]), "=r"(r[1]), "=r"(r[2]), "=r"(r[3]) : "r"(addr));
}
__device__ __forceinline__ void ldsm4t(uint32_t* r, uint32_t addr) {
    asm volatile("ldmatrix.sync.aligned.m8n8.x4.trans.shared.b16 {%0,%1,%2,%3}, [%4];"
        : "=r"(r[0]), "=r"(r[1]), "=r"(r[2]), "=r"(r[3]) : "r"(addr));
}
__device__ __forceinline__ void mma_f16(float* c, const uint32_t* a, const uint32_t* b) {
    asm volatile(
        "mma.sync.aligned.m16n8k16.row.col.f32.f16.f16.f32 "
        "{%0,%1,%2,%3}, {%4,%5,%6,%7}, {%8,%9}, {%0,%1,%2,%3};"
        : "+f"(c[0]), "+f"(c[1]), "+f"(c[2]), "+f"(c[3])
        : "r"(a[0]), "r"(a[1]), "r"(a[2]), "r"(a[3]), "r"(b[0]), "r"(b[1]));
}

__device__ __forceinline__ uint32_t pk2h(__half a, __half b) {
    return (uint32_t)__half_as_ushort(a) | ((uint32_t)__half_as_ushort(b) << 16);
}
__device__ __forceinline__ void split4h(float4 v, uint2& uh, uint2& ul) {
    __half h0 = __float2half_rn(v.x), h1 = __float2half_rn(v.y);
    __half h2 = __float2half_rn(v.z), h3 = __float2half_rn(v.w);
    __half l0 = __float2half_rn(v.x - __half2float(h0));
    __half l1 = __float2half_rn(v.y - __half2float(h1));
    __half l2 = __float2half_rn(v.z - __half2float(h2));
    __half l3 = __float2half_rn(v.w - __half2float(h3));
    uh.x = pk2h(h0, h1); uh.y = pk2h(h2, h3);
    ul.x = pk2h(l0, l1); ul.y = pk2h(l2, l3);
}

// ---------------- init ----------------
__global__ void zero_kernel() {
    int i = blockIdx.x * blockDim.x + threadIdx.x;
    if (i < NPAD) g_ltok[i] = -1;
    if (i < E_EXP) { g_count[i] = 0; g_smsum[i] = 0.0f; g_cursor[i] = 0; }
}

// ---------------- weight convert: fp32 -> fp16 (hi only), all three tensors ----------------
__global__ void convW_kernel(const float4* __restrict__ w1,
                             const float4* __restrict__ w2,
                             const float4* __restrict__ wp, int n4) {
    int i = blockIdx.x * blockDim.x + threadIdx.x;
    if (i >= n4) return;
    const float4* src;
    uint2* dst;
    if (blockIdx.y == 0)      { src = w1; dst = (uint2*)g_w1h; }
    else if (blockIdx.y == 1) { src = w2; dst = (uint2*)g_w2h; }
    else                      { src = wp; dst = (uint2*)g_wph; }
    float4 v = src[i];
    uint2 o;
    o.x = pk2h(__float2half_rn(v.x), __float2half_rn(v.y));
    o.y = pk2h(__float2half_rn(v.z), __float2half_rn(v.w));
    dst[i] = o;
}

// ---------------- gating ----------------
__global__ void gate_kernel(const float* __restrict__ x,
                            const float* __restrict__ noise,
                            const float* __restrict__ gw,
                            const float* __restrict__ nw,
                            float* __restrict__ out) {
    int t = blockIdx.x;
    int w = threadIdx.x >> 5;
    int lane = threadIdx.x & 31;
    __shared__ float logit[E_EXP];

    const float* xr = x + (size_t)t * D_DIM;
    float s = 0.0f;
    for (int d = lane; d < D_DIM; d += 32)
        s += xr[d] * gw[d * E_EXP + w];
    #pragma unroll
    for (int o = 16; o; o >>= 1) s += __shfl_xor_sync(0xffffffffu, s, o);
    if (lane == 0) logit[w] = s;
    __syncthreads();

    if (threadIdx.x == 0) {
        float l[E_EXP], ln[E_EXP];
        float m = -1e30f;
        #pragma unroll
        for (int e = 0; e < E_EXP; e++) { l[e] = logit[e]; m = fmaxf(m, l[e]); }
        float sum = 0.0f;
        float ex[E_EXP];
        #pragma unroll
        for (int e = 0; e < E_EXP; e++) { ex[e] = expf(l[e] - m); sum += ex[e]; }
        float inv = 1.0f / sum;
        #pragma unroll
        for (int e = 0; e < E_EXP; e++) atomicAdd(&g_smsum[e], ex[e] * inv);

        #pragma unroll
        for (int e = 0; e < E_EXP; e++) ln[e] = l[e] + noise[t * E_EXP + e] * nw[e];

        int b0 = 0;
        #pragma unroll
        for (int e = 1; e < E_EXP; e++) if (ln[e] > ln[b0]) b0 = e;
        int b1 = (b0 == 0) ? 1 : 0;
        #pragma unroll
        for (int e = 0; e < E_EXP; e++) if (e != b0 && ln[e] > ln[b1]) b1 = e;

        float v0 = ln[b0], v1 = ln[b1];
        float mm = fmaxf(v0, v1);
        float e0 = expf(v0 - mm), e1 = expf(v1 - mm);
        float denom = 1.0f / (e0 + e1);

        g_e[t][0] = b0; g_e[t][1] = b1;
        g_g[t][0] = e0 * denom; g_g[t][1] = e1 * denom;
        atomicAdd(&g_count[b0], 1);
        atomicAdd(&g_count[b1], 1);
        out[OUT_IDS + t * K_TOP + 0] = (float)b0;
        out[OUT_IDS + t * K_TOP + 1] = (float)b1;
    }
}

// ---------------- padded offsets + lb loss ----------------
__global__ void offsets_kernel(float* __restrict__ out) {
    if (threadIdx.x == 0) {
        int acc = 0;
        #pragma unroll
        for (int e = 0; e < E_EXP; e++) {
            g_offset[e] = acc;
            acc += (g_count[e] + 127) & ~127;
        }
        g_offset[E_EXP] = acc;
        float loss = 0.0f;
        #pragma unroll
        for (int e = 0; e < E_EXP; e++) {
            float gm = g_smsum[e] / (float)T_TOK - 1.0f / (float)E_EXP;
            loss += gm * gm;
        }
        out[OUT_LOSS] = (loss / (float)E_EXP) * 0.01f;
    }
}

// ---------------- scatter ----------------
__global__ void scatter_kernel() {
    int t = blockIdx.x * blockDim.x + threadIdx.x;
    if (t >= T_TOK) return;
    #pragma unroll
    for (int k = 0; k < K_TOP; k++) {
        int e = g_e[t][k];
        int pos = atomicAdd(&g_cursor[e], 1);
        int r = g_offset[e] + pos;
        g_ltok[r] = t;
        g_rows[t][k] = r;
    }
}

// ---------------- gather + fp16 hi/lo split of routed x rows ----------------
__global__ void gatherx_kernel(const float* __restrict__ x) {
    int r = blockIdx.x;
    int d = threadIdx.x * 4;
    int t = g_ltok[r];
    uint2 uh = make_uint2(0, 0), ul = make_uint2(0, 0);
    if (t >= 0) {
        float4 v = *(const float4*)(x + (size_t)t * D_DIM + d);
        split4h(v, uh, ul);
    }
    *(uint2*)(g_xgh + (size_t)r * D_DIM + d) = uh;
    *(uint2*)(g_xgl + (size_t)r * D_DIM + d) = ul;
}

// ---------------- HMMA grouped GEMM 1: act = (x@w1+b1)*silu(x@w2+b2) ----------------
// 128 rows x 64 h-cols, K=768, fp16 2-pass (xh*w + xl*w), cp.async double buffer
__global__ __launch_bounds__(256) void gemm1_mma(
        const float* __restrict__ b1, const float* __restrict__ b2) {
    int e = blockIdx.z;
    int cnt = g_count[e];
    int m0 = blockIdx.x * 128;
    if (m0 >= cnt) return;
    int rbase = g_offset[e] + m0;
    int hb = blockIdx.y * 64;
    int tid = threadIdx.x;
    int lane = tid & 31, wid = tid >> 5;
    int wm = (wid & 3) * 32, wn = (wid >> 2) * 32;

    extern __shared__ char smraw[];
    __half* smb = (__half*)smraw;
    const int A_SZ = 128 * 40;   // stride 40 halfs (80B)
    const int B_SZ = 32 * 72;    // stride 72 halfs (144B)
    const int STG  = 2 * A_SZ + 2 * B_SZ;        // xh, xl, w1h, w2h
    const uint32_t STGB = (uint32_t)STG * 2;

    int a_row = tid >> 1, a_half = tid & 1;
    int b_row = tid >> 3, b_col = (tid & 7) * 8;

    const __half* xh_p = g_xgh + (size_t)(rbase + a_row) * D_DIM + a_half * 16;
    const __half* xl_p = g_xgl + (size_t)(rbase + a_row) * D_DIM + a_half * 16;
    const __half* w1_p = g_w1h + (size_t)e * D_DIM * H_DIM + hb + b_col;
    const __half* w2_p = g_w2h + (size_t)e * D_DIM * H_DIM + hb + b_col;

    uint32_t smbase = s2u(smb);
    uint32_t dAh = smbase + (uint32_t)(a_row * 40 + a_half * 16) * 2;
    uint32_t dAl = dAh + A_SZ * 2;
    uint32_t dB1 = smbase + (uint32_t)(2 * A_SZ + b_row * 72 + b_col) * 2;
    uint32_t dB2 = dB1 + B_SZ * 2;

    float accH[2][4][4], accG[2][4][4];
    #pragma unroll
    for (int i = 0; i < 2; i++)
        #pragma unroll
        for (int j = 0; j < 4; j++)
            #pragma unroll
            for (int k = 0; k < 4; k++) { accH[i][j][k] = 0.f; accG[i][j][k] = 0.f; }

    const int NK = D_DIM / 32;   // 24

    {
        cp16(dAh, xh_p);  cp16(dAh + 16, xh_p + 8);
        cp16(dAl, xl_p);  cp16(dAl + 16, xl_p + 8);
        size_t rk = (size_t)b_row * H_DIM;
        cp16(dB1, w1_p + rk);
        cp16(dB2, w2_p + rk);
        CP_COMMIT();
    }

    for (int kc = 0; kc < NK; kc++) {
        int p = kc & 1;
        if (kc + 1 < NK) {
            int k0 = (kc + 1) * 32;
            uint32_t so = (uint32_t)((kc + 1) & 1) * STGB;
            cp16(dAh + so, xh_p + k0);  cp16(dAh + so + 16, xh_p + k0 + 8);
            cp16(dAl + so, xl_p + k0);  cp16(dAl + so + 16, xl_p + k0 + 8);
            size_t rk = (size_t)(k0 + b_row) * H_DIM;
            cp16(dB1 + so, w1_p + rk);
            cp16(dB2 + so, w2_p + rk);
            CP_COMMIT();
            CP_WAIT1();
        } else {
            CP_WAIT0();
        }
        __syncthreads();

        __half* sAh = smb + p * STG;
        __half* sAl = sAh + A_SZ;
        __half* sB1 = sAl + A_SZ;
        __half* sB2 = sB1 + B_SZ;

        #pragma unroll
        for (int k16 = 0; k16 < 32; k16 += 16) {
            uint32_t ah[2][4], al[2][4];
            #pragma unroll
            for (int mt = 0; mt < 2; mt++) {
                int ro = wm + mt * 16 + (lane & 15);
                int co = k16 + ((lane >> 4) << 3);
                ldsm4(ah[mt], s2u(sAh + ro * 40 + co));
                ldsm4(al[mt], s2u(sAl + ro * 40 + co));
            }
            #pragma unroll
            for (int q = 0; q < 2; q++) {
                int ro = k16 + (lane & 15);
                int co = wn + q * 16 + ((lane >> 4) << 3);
                uint32_t rb1[4], rb2[4];
                ldsm4t(rb1, s2u(sB1 + ro * 72 + co));
                ldsm4t(rb2, s2u(sB2 + ro * 72 + co));
                #pragma unroll
                for (int mt = 0; mt < 2; mt++)
                    #pragma unroll
                    for (int j = 0; j < 2; j++) {
                        mma_f16(accH[mt][q * 2 + j], ah[mt], &rb1[j * 2]);
                        mma_f16(accH[mt][q * 2 + j], al[mt], &rb1[j * 2]);
                        mma_f16(accG[mt][q * 2 + j], ah[mt], &rb2[j * 2]);
                        mma_f16(accG[mt][q * 2 + j], al[mt], &rb2[j * 2]);
                    }
            }
        }
        __syncthreads();
    }

    // epilogue: act = (h+b1)*silu(g+b2), stored fp16 hi/lo
    const float* b1p = b1 + (size_t)e * H_DIM + hb;
    const float* b2p = b2 + (size_t)e * H_DIM + hb;
    #pragma unroll
    for (int mt = 0; mt < 2; mt++) {
        int row0 = rbase + wm + mt * 16 + (lane >> 2);
        #pragma unroll
        for (int nt = 0; nt < 4; nt++) {
            int cl = wn + nt * 8 + (lane & 3) * 2;
            float bb1a = b1p[cl], bb1b = b1p[cl + 1];
            float bb2a = b2p[cl], bb2b = b2p[cl + 1];
            #pragma unroll
            for (int hf = 0; hf < 2; hf++) {
                float hv0 = accH[mt][nt][hf * 2 + 0] + bb1a;
                float hv1 = accH[mt][nt][hf * 2 + 1] + bb1b;
                float gv0 = accG[mt][nt][hf * 2 + 0] + bb2a;
                float gv1 = accG[mt][nt][hf * 2 + 1] + bb2b;
                float a0 = hv0 * (gv0 / (1.0f + expf(-gv0)));
                float a1 = hv1 * (gv1 / (1.0f + expf(-gv1)));
                __half h0 = __float2half_rn(a0), h1 = __float2half_rn(a1);
                uint32_t vh = pk2h(h0, h1);
                uint32_t vl = pk2h(__float2half_rn(a0 - __half2float(h0)),
                                   __float2half_rn(a1 - __half2float(h1)));
                size_t off = (size_t)(row0 + hf * 8) * H_DIM + hb + cl;
                *(uint32_t*)(g_acth + off) = vh;
                *(uint32_t*)(g_actl + off) = vl;
            }
        }
    }
}

// ---------------- HMMA grouped GEMM 2: y = act @ wp + bp ----------------
// 128 rows x 128 d-cols, K=3072, fp16 2-pass, cp.async double buffer
__global__ __launch_bounds__(256) void gemm2_mma(const float* __restrict__ bp) {
    int e = blockIdx.z;
    int cnt = g_count[e];
    int m0 = blockIdx.x * 128;
    if (m0 >= cnt) return;
    int rbase = g_offset[e] + m0;
    int db = blockIdx.y * 128;
    int tid = threadIdx.x;
    int lane = tid & 31, wid = tid >> 5;
    int wm = (wid & 3) * 32, wn = (wid >> 2) * 64;

    extern __shared__ char smraw[];
    __half* smb = (__half*)smraw;
    const int A_SZ = 128 * 40;
    const int B_SZ = 32 * 136;   // stride 136 halfs (272B)
    const int STG  = 2 * A_SZ + B_SZ;
    const uint32_t STGB = (uint32_t)STG * 2;

    int a_row = tid >> 1, a_half = tid & 1;
    int b_row = tid >> 3, b_col = (tid & 7) * 16;

    const __half* ah_p = g_acth + (size_t)(rbase + a_row) * H_DIM + a_half * 16;
    const __half* al_p = g_actl + (size_t)(rbase + a_row) * H_DIM + a_half * 16;
    const __half* wp_p = g_wph + (size_t)e * H_DIM * D_DIM + db + b_col;

    uint32_t smbase = s2u(smb);
    uint32_t dAh = smbase + (uint32_t)(a_row * 40 + a_half * 16) * 2;
    uint32_t dAl = dAh + A_SZ * 2;
    uint32_t dB  = smbase + (uint32_t)(2 * A_SZ + b_row * 136 + b_col) * 2;

    float acc[2][8][4];
    #pragma unroll
    for (int i = 0; i < 2; i++)
        #pragma unroll
        for (int j = 0; j < 8; j++)
            #pragma unroll
            for (int k = 0; k < 4; k++) acc[i][j][k] = 0.f;

    const int NK = H_DIM / 32;   // 96

    {
        cp16(dAh, ah_p);  cp16(dAh + 16, ah_p + 8);
        cp16(dAl, al_p);  cp16(dAl + 16, al_p + 8);
        size_t rk = (size_t)b_row * D_DIM;
        cp16(dB, wp_p + rk);  cp16(dB + 16, wp_p + rk + 8);
        CP_COMMIT();
    }

    for (int kc = 0; kc < NK; kc++) {
        int p = kc & 1;
        if (kc + 1 < NK) {
            int k0 = (kc + 1) * 32;
            uint32_t so = (uint32_t)((kc + 1) & 1) * STGB;
            cp16(dAh + so, ah_p + k0);  cp16(dAh + so + 16, ah_p + k0 + 8);
            cp16(dAl + so, al_p + k0);  cp16(dAl + so + 16, al_p + k0 + 8);
            size_t rk = (size_t)(k0 + b_row) * D_DIM;
            cp16(dB + so, wp_p + rk);  cp16(dB + so + 16, wp_p + rk + 8);
            CP_COMMIT();
            CP_WAIT1();
        } else {
            CP_WAIT0();
        }
        __syncthreads();

        __half* sAh = smb + p * STG;
        __half* sAl = sAh + A_SZ;
        __half* sB  = sAl + A_SZ;

        #pragma unroll
        for (int k16 = 0; k16 < 32; k16 += 16) {
            uint32_t ah[2][4], al[2][4];
            #pragma unroll
            for (int mt = 0; mt < 2; mt++) {
                int ro = wm + mt * 16 + (lane & 15);
                int co = k16 + ((lane >> 4) << 3);
                ldsm4(ah[mt], s2u(sAh + ro * 40 + co));
                ldsm4(al[mt], s2u(sAl + ro * 40 + co));
            }
            #pragma unroll
            for (int q = 0; q < 4; q++) {
                int ro = k16 + (lane & 15);
                int co = wn + q * 16 + ((lane >> 4) << 3);
                uint32_t rb[4];
                ldsm4t(rb, s2u(sB + ro * 136 + co));
                #pragma unroll
                for (int mt = 0; mt < 2; mt++)
                    #pragma unroll
                    for (int j = 0; j < 2; j++) {
                        mma_f16(acc[mt][q * 2 + j], ah[mt], &rb[j * 2]);
                        mma_f16(acc[mt][q * 2 + j], al[mt], &rb[j * 2]);
                    }
            }
        }
        __syncthreads();
    }

    const float* bpp = bp + (size_t)e * D_DIM + db;
    #pragma unroll
    for (int mt = 0; mt < 2; mt++) {
        int row0 = rbase + wm + mt * 16 + (lane >> 2);
        #pragma unroll
        for (int nt = 0; nt < 8; nt++) {
            int cl = wn + nt * 8 + (lane & 3) * 2;
            float ba = bpp[cl], bb = bpp[cl + 1];
            #pragma unroll
            for (int hf = 0; hf < 2; hf++) {
                float2 v;
                v.x = acc[mt][nt][hf * 2 + 0] + ba;
                v.y = acc[mt][nt][hf * 2 + 1] + bb;
                *(float2*)(g_y + (size_t)(row0 + hf * 8) * D_DIM + db + cl) = v;
            }
        }
    }
}

// ---------------- final combine: out[t] = g0*y[r0] + g1*y[r1] ----------------
__global__ void combine_kernel(float* __restrict__ out) {
    int t = blockIdx.x;
    int d = threadIdx.x * 4;
    int r0 = g_rows[t][0], r1 = g_rows[t][1];
    float g0 = g_g[t][0], g1 = g_g[t][1];
    float4 a = *(const float4*)(g_y + (size_t)r0 * D_DIM + d);
    float4 b = *(const float4*)(g_y + (size_t)r1 * D_DIM + d);
    float4 o;
    o.x = g0 * a.x + g1 * b.x;
    o.y = g0 * a.y + g1 * b.y;
    o.z = g0 * a.z + g1 * b.z;
    o.w = g0 * a.w + g1 * b.w;
    *(float4*)(out + (size_t)t * D_DIM + d) = o;
}

// ---------------- launch ----------------
extern "C" void kernel_launch(void* const* d_in, const int* in_sizes, int n_in,
                              void* d_out, int out_size) {
    const float* x     = (const float*)d_in[0];
    const float* noise = (const float*)d_in[1];
    const float* gw    = (const float*)d_in[2];
    const float* nw    = (const float*)d_in[3];
    const float* w1    = (const float*)d_in[4];
    const float* b1    = (const float*)d_in[5];
    const float* w2    = (const float*)d_in[6];
    const float* b2    = (const float*)d_in[7];
    const float* wp    = (const float*)d_in[8];
    const float* bp    = (const float*)d_in[9];
    float* out = (float*)d_out;

    const int SM1 = 2 * (2 * 128 * 40 + 2 * 32 * 72) * 2;   // 59392 B
    const int SM2 = 2 * (2 * 128 * 40 + 32 * 136) * 2;      // 58368 B
    cudaFuncSetAttribute(gemm1_mma, cudaFuncAttributeMaxDynamicSharedMemorySize, SM1);
    cudaFuncSetAttribute(gemm2_mma, cudaFuncAttributeMaxDynamicSharedMemorySize, SM2);

    const int NW4 = E_EXP * D_DIM * H_DIM / 4;
    convW_kernel<<<dim3((NW4 + 255) / 256, 3), 256>>>(
        (const float4*)w1, (const float4*)w2, (const float4*)wp, NW4);

    zero_kernel<<<(NPAD + 255) / 256, 256>>>();
    gate_kernel<<<T_TOK, 256>>>(x, noise, gw, nw, out);
    offsets_kernel<<<1, 32>>>(out);
    scatter_kernel<<<(T_TOK + 255) / 256, 256>>>();
    gatherx_kernel<<<NPAD, 192>>>(x);

    gemm1_mma<<<dim3(16, H_DIM / 64, E_EXP), 256, SM1>>>(b1, b2);
    gemm2_mma<<<dim3(16, D_DIM / 128, E_EXP), 256, SM2>>>(bp);

    combine_kernel<<<T_TOK, 192>>>(out);
}

// round 12
// speedup vs baseline: 4.6432x; 1.4237x over previous
#include <cuda_runtime.h>
#include <cuda_fp16.h>
#include <math.h>
#include <stdint.h>

#define T_TOK 2048
#define D_DIM 768
#define E_EXP 8
#define K_TOP 2
#define H_DIM 3072
#define NPAD  5120

#define OUT_IDS  (T_TOK * D_DIM)
#define OUT_LOSS (T_TOK * D_DIM + T_TOK * K_TOP)

// ---------------- device scratch ----------------
__device__ int   g_e[T_TOK][K_TOP];
__device__ float g_g[T_TOK][K_TOP];
__device__ int   g_rows[T_TOK][K_TOP];
__device__ int   g_count[E_EXP];
__device__ int   g_offset[E_EXP + 1];
__device__ int   g_cursor[E_EXP];
__device__ float g_smsum[E_EXP];
__device__ int   g_ltok[NPAD];

__device__ __half g_xgh[(size_t)NPAD * D_DIM];
__device__ __half g_w1h[(size_t)E_EXP * D_DIM * H_DIM];
__device__ __half g_w2h[(size_t)E_EXP * D_DIM * H_DIM];
__device__ __half g_wph[(size_t)E_EXP * H_DIM * D_DIM];
__device__ __half g_acth[(size_t)NPAD * H_DIM];
__device__ float g_y[(size_t)NPAD * D_DIM];

// ---------------- helpers ----------------
__device__ __forceinline__ uint32_t s2u(const void* p) {
    return (uint32_t)__cvta_generic_to_shared(p);
}
__device__ __forceinline__ void cp16(uint32_t dst, const void* src) {
    asm volatile("cp.async.ca.shared.global [%0], [%1], 16;" :: "r"(dst), "l"(src));
}
#define CP_COMMIT() asm volatile("cp.async.commit_group;")
#define CP_WAIT1()  asm volatile("cp.async.wait_group 1;")
#define CP_WAIT0()  asm volatile("cp.async.wait_group 0;")

__device__ __forceinline__ void ldsm4(uint32_t* r, uint32_t addr) {
    asm volatile("ldmatrix.sync.aligned.m8n8.x4.shared.b16 {%0,%1,%2,%3}, [%4];"
        : "=r"(r[0]), "=r"(r[1]), "=r"(r[2]), "=r"(r[3]) : "r"(addr));
}
__device__ __forceinline__ void ldsm4t(uint32_t* r, uint32_t addr) {
    asm volatile("ldmatrix.sync.aligned.m8n8.x4.trans.shared.b16 {%0,%1,%2,%3}, [%4];"
        : "=r"(r[0]), "=r"(r[1]), "=r"(r[2]), "=r"(r[3]) : "r"(addr));
}
__device__ __forceinline__ void mma_f16(float* c, const uint32_t* a, const uint32_t* b) {
    asm volatile(
        "mma.sync.aligned.m16n8k16.row.col.f32.f16.f16.f32 "
        "{%0,%1,%2,%3}, {%4,%5,%6,%7}, {%8,%9}, {%0,%1,%2,%3};"
        : "+f"(c[0]), "+f"(c[1]), "+f"(c[2]), "+f"(c[3])
        : "r"(a[0]), "r"(a[1]), "r"(a[2]), "r"(a[3]), "r"(b[0]), "r"(b[1]));
}

__device__ __forceinline__ uint32_t pk2h(__half a, __half b) {
    return (uint32_t)__half_as_ushort(a) | ((uint32_t)__half_as_ushort(b) << 16);
}

// ---------------- init ----------------
__global__ void zero_kernel() {
    int i = blockIdx.x * blockDim.x + threadIdx.x;
    if (i < NPAD) g_ltok[i] = -1;
    if (i < E_EXP) { g_count[i] = 0; g_smsum[i] = 0.0f; g_cursor[i] = 0; }
}

// ---------------- weight convert: fp32 -> fp16, all three tensors ----------------
__global__ void convW_kernel(const float4* __restrict__ w1,
                             const float4* __restrict__ w2,
                             const float4* __restrict__ wp, int n4) {
    int i = blockIdx.x * blockDim.x + threadIdx.x;
    if (i >= n4) return;
    const float4* src;
    uint2* dst;
    if (blockIdx.y == 0)      { src = w1; dst = (uint2*)g_w1h; }
    else if (blockIdx.y == 1) { src = w2; dst = (uint2*)g_w2h; }
    else                      { src = wp; dst = (uint2*)g_wph; }
    float4 v = src[i];
    uint2 o;
    o.x = pk2h(__float2half_rn(v.x), __float2half_rn(v.y));
    o.y = pk2h(__float2half_rn(v.z), __float2half_rn(v.w));
    dst[i] = o;
}

// ---------------- gating ----------------
__global__ void gate_kernel(const float* __restrict__ x,
                            const float* __restrict__ noise,
                            const float* __restrict__ gw,
                            const float* __restrict__ nw,
                            float* __restrict__ out) {
    int t = blockIdx.x;
    int w = threadIdx.x >> 5;
    int lane = threadIdx.x & 31;
    __shared__ float logit[E_EXP];

    const float* xr = x + (size_t)t * D_DIM;
    float s = 0.0f;
    for (int d = lane; d < D_DIM; d += 32)
        s += xr[d] * gw[d * E_EXP + w];
    #pragma unroll
    for (int o = 16; o; o >>= 1) s += __shfl_xor_sync(0xffffffffu, s, o);
    if (lane == 0) logit[w] = s;
    __syncthreads();

    if (threadIdx.x == 0) {
        float l[E_EXP], ln[E_EXP];
        float m = -1e30f;
        #pragma unroll
        for (int e = 0; e < E_EXP; e++) { l[e] = logit[e]; m = fmaxf(m, l[e]); }
        float sum = 0.0f;
        float ex[E_EXP];
        #pragma unroll
        for (int e = 0; e < E_EXP; e++) { ex[e] = expf(l[e] - m); sum += ex[e]; }
        float inv = 1.0f / sum;
        #pragma unroll
        for (int e = 0; e < E_EXP; e++) atomicAdd(&g_smsum[e], ex[e] * inv);

        #pragma unroll
        for (int e = 0; e < E_EXP; e++) ln[e] = l[e] + noise[t * E_EXP + e] * nw[e];

        int b0 = 0;
        #pragma unroll
        for (int e = 1; e < E_EXP; e++) if (ln[e] > ln[b0]) b0 = e;
        int b1 = (b0 == 0) ? 1 : 0;
        #pragma unroll
        for (int e = 0; e < E_EXP; e++) if (e != b0 && ln[e] > ln[b1]) b1 = e;

        float v0 = ln[b0], v1 = ln[b1];
        float mm = fmaxf(v0, v1);
        float e0 = expf(v0 - mm), e1 = expf(v1 - mm);
        float denom = 1.0f / (e0 + e1);

        g_e[t][0] = b0; g_e[t][1] = b1;
        g_g[t][0] = e0 * denom; g_g[t][1] = e1 * denom;
        atomicAdd(&g_count[b0], 1);
        atomicAdd(&g_count[b1], 1);
        out[OUT_IDS + t * K_TOP + 0] = (float)b0;
        out[OUT_IDS + t * K_TOP + 1] = (float)b1;
    }
}

// ---------------- padded offsets + lb loss ----------------
__global__ void offsets_kernel(float* __restrict__ out) {
    if (threadIdx.x == 0) {
        int acc = 0;
        #pragma unroll
        for (int e = 0; e < E_EXP; e++) {
            g_offset[e] = acc;
            acc += (g_count[e] + 127) & ~127;
        }
        g_offset[E_EXP] = acc;
        float loss = 0.0f;
        #pragma unroll
        for (int e = 0; e < E_EXP; e++) {
            float gm = g_smsum[e] / (float)T_TOK - 1.0f / (float)E_EXP;
            loss += gm * gm;
        }
        out[OUT_LOSS] = (loss / (float)E_EXP) * 0.01f;
    }
}

// ---------------- scatter ----------------
__global__ void scatter_kernel() {
    int t = blockIdx.x * blockDim.x + threadIdx.x;
    if (t >= T_TOK) return;
    #pragma unroll
    for (int k = 0; k < K_TOP; k++) {
        int e = g_e[t][k];
        int pos = atomicAdd(&g_cursor[e], 1);
        int r = g_offset[e] + pos;
        g_ltok[r] = t;
        g_rows[t][k] = r;
    }
}

// ---------------- gather routed x rows -> fp16 ----------------
__global__ void gatherx_kernel(const float* __restrict__ x) {
    int r = blockIdx.x;
    int d = threadIdx.x * 4;
    int t = g_ltok[r];
    uint2 uh = make_uint2(0, 0);
    if (t >= 0) {
        float4 v = *(const float4*)(x + (size_t)t * D_DIM + d);
        uh.x = pk2h(__float2half_rn(v.x), __float2half_rn(v.y));
        uh.y = pk2h(__float2half_rn(v.z), __float2half_rn(v.w));
    }
    *(uint2*)(g_xgh + (size_t)r * D_DIM + d) = uh;
}

// ---------------- HMMA grouped GEMM 1: act = (x@w1+b1)*silu(x@w2+b2) ----------------
// 128 rows x 64 h-cols, K=768, fp16 single pass, cp.async double buffer
__global__ __launch_bounds__(256) void gemm1_mma(
        const float* __restrict__ b1, const float* __restrict__ b2) {
    int e = blockIdx.z;
    int cnt = g_count[e];
    int m0 = blockIdx.x * 128;
    if (m0 >= cnt) return;
    int rbase = g_offset[e] + m0;
    int hb = blockIdx.y * 64;
    int tid = threadIdx.x;
    int lane = tid & 31, wid = tid >> 5;
    int wm = (wid & 3) * 32, wn = (wid >> 2) * 32;

    extern __shared__ char smraw[];
    __half* smb = (__half*)smraw;
    const int A_SZ = 128 * 40;   // stride 40 halfs (80B)
    const int B_SZ = 32 * 72;    // stride 72 halfs (144B)
    const int STG  = A_SZ + 2 * B_SZ;           // xh, w1h, w2h
    const uint32_t STGB = (uint32_t)STG * 2;

    int a_row = tid >> 1, a_half = tid & 1;      // 2 thr/row, 32B each
    int b_row = tid >> 3, b_col = (tid & 7) * 8; // 8 thr/row, 16B per mat

    const __half* xh_p = g_xgh + (size_t)(rbase + a_row) * D_DIM + a_half * 16;
    const __half* w1_p = g_w1h + (size_t)e * D_DIM * H_DIM + hb + b_col;
    const __half* w2_p = g_w2h + (size_t)e * D_DIM * H_DIM + hb + b_col;

    uint32_t smbase = s2u(smb);
    uint32_t dAh = smbase + (uint32_t)(a_row * 40 + a_half * 16) * 2;
    uint32_t dB1 = smbase + (uint32_t)(A_SZ + b_row * 72 + b_col) * 2;
    uint32_t dB2 = dB1 + B_SZ * 2;

    float accH[2][4][4], accG[2][4][4];
    #pragma unroll
    for (int i = 0; i < 2; i++)
        #pragma unroll
        for (int j = 0; j < 4; j++)
            #pragma unroll
            for (int k = 0; k < 4; k++) { accH[i][j][k] = 0.f; accG[i][j][k] = 0.f; }

    const int NK = D_DIM / 32;   // 24

    {
        cp16(dAh, xh_p);  cp16(dAh + 16, xh_p + 8);
        size_t rk = (size_t)b_row * H_DIM;
        cp16(dB1, w1_p + rk);
        cp16(dB2, w2_p + rk);
        CP_COMMIT();
    }

    for (int kc = 0; kc < NK; kc++) {
        int p = kc & 1;
        if (kc + 1 < NK) {
            int k0 = (kc + 1) * 32;
            uint32_t so = (uint32_t)((kc + 1) & 1) * STGB;
            cp16(dAh + so, xh_p + k0);  cp16(dAh + so + 16, xh_p + k0 + 8);
            size_t rk = (size_t)(k0 + b_row) * H_DIM;
            cp16(dB1 + so, w1_p + rk);
            cp16(dB2 + so, w2_p + rk);
            CP_COMMIT();
            CP_WAIT1();
        } else {
            CP_WAIT0();
        }
        __syncthreads();

        __half* sAh = smb + p * STG;
        __half* sB1 = sAh + A_SZ;
        __half* sB2 = sB1 + B_SZ;

        #pragma unroll
        for (int k16 = 0; k16 < 32; k16 += 16) {
            uint32_t ah[2][4];
            #pragma unroll
            for (int mt = 0; mt < 2; mt++) {
                int ro = wm + mt * 16 + (lane & 15);
                int co = k16 + ((lane >> 4) << 3);
                ldsm4(ah[mt], s2u(sAh + ro * 40 + co));
            }
            #pragma unroll
            for (int q = 0; q < 2; q++) {
                int ro = k16 + (lane & 15);
                int co = wn + q * 16 + ((lane >> 4) << 3);
                uint32_t rb1[4], rb2[4];
                ldsm4t(rb1, s2u(sB1 + ro * 72 + co));
                ldsm4t(rb2, s2u(sB2 + ro * 72 + co));
                #pragma unroll
                for (int mt = 0; mt < 2; mt++)
                    #pragma unroll
                    for (int j = 0; j < 2; j++) {
                        mma_f16(accH[mt][q * 2 + j], ah[mt], &rb1[j * 2]);
                        mma_f16(accG[mt][q * 2 + j], ah[mt], &rb2[j * 2]);
                    }
            }
        }
        __syncthreads();
    }

    // epilogue: act = (h+b1)*silu(g+b2), stored fp16
    const float* b1p = b1 + (size_t)e * H_DIM + hb;
    const float* b2p = b2 + (size_t)e * H_DIM + hb;
    #pragma unroll
    for (int mt = 0; mt < 2; mt++) {
        int row0 = rbase + wm + mt * 16 + (lane >> 2);
        #pragma unroll
        for (int nt = 0; nt < 4; nt++) {
            int cl = wn + nt * 8 + (lane & 3) * 2;
            float bb1a = b1p[cl], bb1b = b1p[cl + 1];
            float bb2a = b2p[cl], bb2b = b2p[cl + 1];
            #pragma unroll
            for (int hf = 0; hf < 2; hf++) {
                float hv0 = accH[mt][nt][hf * 2 + 0] + bb1a;
                float hv1 = accH[mt][nt][hf * 2 + 1] + bb1b;
                float gv0 = accG[mt][nt][hf * 2 + 0] + bb2a;
                float gv1 = accG[mt][nt][hf * 2 + 1] + bb2b;
                float a0 = hv0 * (gv0 / (1.0f + expf(-gv0)));
                float a1 = hv1 * (gv1 / (1.0f + expf(-gv1)));
                uint32_t vh = pk2h(__float2half_rn(a0), __float2half_rn(a1));
                size_t off = (size_t)(row0 + hf * 8) * H_DIM + hb + cl;
                *(uint32_t*)(g_acth + off) = vh;
            }
        }
    }
}

// ---------------- HMMA grouped GEMM 2: y = act @ wp + bp ----------------
// 128 rows x 128 d-cols, K=3072, fp16 single pass, cp.async double buffer
__global__ __launch_bounds__(256) void gemm2_mma(const float* __restrict__ bp) {
    int e = blockIdx.z;
    int cnt = g_count[e];
    int m0 = blockIdx.x * 128;
    if (m0 >= cnt) return;
    int rbase = g_offset[e] + m0;
    int db = blockIdx.y * 128;
    int tid = threadIdx.x;
    int lane = tid & 31, wid = tid >> 5;
    int wm = (wid & 3) * 32, wn = (wid >> 2) * 64;

    extern __shared__ char smraw[];
    __half* smb = (__half*)smraw;
    const int A_SZ = 128 * 40;
    const int B_SZ = 32 * 136;   // stride 136 halfs (272B)
    const int STG  = A_SZ + B_SZ;
    const uint32_t STGB = (uint32_t)STG * 2;

    int a_row = tid >> 1, a_half = tid & 1;
    int b_row = tid >> 3, b_col = (tid & 7) * 16;

    const __half* ah_p = g_acth + (size_t)(rbase + a_row) * H_DIM + a_half * 16;
    const __half* wp_p = g_wph + (size_t)e * H_DIM * D_DIM + db + b_col;

    uint32_t smbase = s2u(smb);
    uint32_t dAh = smbase + (uint32_t)(a_row * 40 + a_half * 16) * 2;
    uint32_t dB  = smbase + (uint32_t)(A_SZ + b_row * 136 + b_col) * 2;

    float acc[2][8][4];
    #pragma unroll
    for (int i = 0; i < 2; i++)
        #pragma unroll
        for (int j = 0; j < 8; j++)
            #pragma unroll
            for (int k = 0; k < 4; k++) acc[i][j][k] = 0.f;

    const int NK = H_DIM / 32;   // 96

    {
        cp16(dAh, ah_p);  cp16(dAh + 16, ah_p + 8);
        size_t rk = (size_t)b_row * D_DIM;
        cp16(dB, wp_p + rk);  cp16(dB + 16, wp_p + rk + 8);
        CP_COMMIT();
    }

    for (int kc = 0; kc < NK; kc++) {
        int p = kc & 1;
        if (kc + 1 < NK) {
            int k0 = (kc + 1) * 32;
            uint32_t so = (uint32_t)((kc + 1) & 1) * STGB;
            cp16(dAh + so, ah_p + k0);  cp16(dAh + so + 16, ah_p + k0 + 8);
            size_t rk = (size_t)(k0 + b_row) * D_DIM;
            cp16(dB + so, wp_p + rk);  cp16(dB + so + 16, wp_p + rk + 8);
            CP_COMMIT();
            CP_WAIT1();
        } else {
            CP_WAIT0();
        }
        __syncthreads();

        __half* sAh = smb + p * STG;
        __half* sB  = sAh + A_SZ;

        #pragma unroll
        for (int k16 = 0; k16 < 32; k16 += 16) {
            uint32_t ah[2][4];
            #pragma unroll
            for (int mt = 0; mt < 2; mt++) {
                int ro = wm + mt * 16 + (lane & 15);
                int co = k16 + ((lane >> 4) << 3);
                ldsm4(ah[mt], s2u(sAh + ro * 40 + co));
            }
            #pragma unroll
            for (int q = 0; q < 4; q++) {
                int ro = k16 + (lane & 15);
                int co = wn + q * 16 + ((lane >> 4) << 3);
                uint32_t rb[4];
                ldsm4t(rb, s2u(sB + ro * 136 + co));
                #pragma unroll
                for (int mt = 0; mt < 2; mt++)
                    #pragma unroll
                    for (int j = 0; j < 2; j++)
                        mma_f16(acc[mt][q * 2 + j], ah[mt], &rb[j * 2]);
            }
        }
        __syncthreads();
    }

    const float* bpp = bp + (size_t)e * D_DIM + db;
    #pragma unroll
    for (int mt = 0; mt < 2; mt++) {
        int row0 = rbase + wm + mt * 16 + (lane >> 2);
        #pragma unroll
        for (int nt = 0; nt < 8; nt++) {
            int cl = wn + nt * 8 + (lane & 3) * 2;
            float ba = bpp[cl], bb = bpp[cl + 1];
            #pragma unroll
            for (int hf = 0; hf < 2; hf++) {
                float2 v;
                v.x = acc[mt][nt][hf * 2 + 0] + ba;
                v.y = acc[mt][nt][hf * 2 + 1] + bb;
                *(float2*)(g_y + (size_t)(row0 + hf * 8) * D_DIM + db + cl) = v;
            }
        }
    }
}

// ---------------- final combine: out[t] = g0*y[r0] + g1*y[r1] ----------------
__global__ void combine_kernel(float* __restrict__ out) {
    int t = blockIdx.x;
    int d = threadIdx.x * 4;
    int r0 = g_rows[t][0], r1 = g_rows[t][1];
    float g0 = g_g[t][0], g1 = g_g[t][1];
    float4 a = *(const float4*)(g_y + (size_t)r0 * D_DIM + d);
    float4 b = *(const float4*)(g_y + (size_t)r1 * D_DIM + d);
    float4 o;
    o.x = g0 * a.x + g1 * b.x;
    o.y = g0 * a.y + g1 * b.y;
    o.z = g0 * a.z + g1 * b.z;
    o.w = g0 * a.w + g1 * b.w;
    *(float4*)(out + (size_t)t * D_DIM + d) = o;
}

// ---------------- launch ----------------
extern "C" void kernel_launch(void* const* d_in, const int* in_sizes, int n_in,
                              void* d_out, int out_size) {
    const float* x     = (const float*)d_in[0];
    const float* noise = (const float*)d_in[1];
    const float* gw    = (const float*)d_in[2];
    const float* nw    = (const float*)d_in[3];
    const float* w1    = (const float*)d_in[4];
    const float* b1    = (const float*)d_in[5];
    const float* w2    = (const float*)d_in[6];
    const float* b2    = (const float*)d_in[7];
    const float* wp    = (const float*)d_in[8];
    const float* bp    = (const float*)d_in[9];
    float* out = (float*)d_out;

    const int SM1 = 2 * (128 * 40 + 2 * 32 * 72) * 2;   // 38912 B
    const int SM2 = 2 * (128 * 40 + 32 * 136) * 2;      // 37888 B
    cudaFuncSetAttribute(gemm1_mma, cudaFuncAttributeMaxDynamicSharedMemorySize, SM1);
    cudaFuncSetAttribute(gemm2_mma, cudaFuncAttributeMaxDynamicSharedMemorySize, SM2);

    const int NW4 = E_EXP * D_DIM * H_DIM / 4;
    convW_kernel<<<dim3((NW4 + 255) / 256, 3), 256>>>(
        (const float4*)w1, (const float4*)w2, (const float4*)wp, NW4);

    zero_kernel<<<(NPAD + 255) / 256, 256>>>();
    gate_kernel<<<T_TOK, 256>>>(x, noise, gw, nw, out);
    offsets_kernel<<<1, 32>>>(out);
    scatter_kernel<<<(T_TOK + 255) / 256, 256>>>();
    gatherx_kernel<<<NPAD, 192>>>(x);

    gemm1_mma<<<dim3(16, H_DIM / 64, E_EXP), 256, SM1>>>(b1, b2);
    gemm2_mma<<<dim3(16, D_DIM / 128, E_EXP), 256, SM2>>>(bp);

    combine_kernel<<<T_TOK, 192>>>(out);
}

// round 13
// speedup vs baseline: 4.7666x; 1.0266x over previous
#include <cuda_runtime.h>
#include <cuda_fp16.h>
#include <math.h>
#include <stdint.h>

#define T_TOK 2048
#define D_DIM 768
#define E_EXP 8
#define K_TOP 2
#define H_DIM 3072
#define NPAD  5120

#define OUT_IDS  (T_TOK * D_DIM)
#define OUT_LOSS (T_TOK * D_DIM + T_TOK * K_TOP)

// ---------------- device scratch ----------------
__device__ int   g_e[T_TOK][K_TOP];
__device__ float g_g[T_TOK][K_TOP];
__device__ int   g_rows[T_TOK][K_TOP];
__device__ int   g_count[E_EXP];
__device__ int   g_offset[E_EXP + 1];
__device__ int   g_cursor[E_EXP];
__device__ float g_smsum[E_EXP];
__device__ int   g_ltok[NPAD];

__device__ __half g_xgh[(size_t)NPAD * D_DIM];
__device__ __half g_w1h[(size_t)E_EXP * D_DIM * H_DIM];
__device__ __half g_w2h[(size_t)E_EXP * D_DIM * H_DIM];
__device__ __half g_wph[(size_t)E_EXP * H_DIM * D_DIM];
__device__ __half g_acth[(size_t)NPAD * H_DIM];
__device__ float g_y[(size_t)NPAD * D_DIM];

// ---------------- helpers ----------------
__device__ __forceinline__ uint32_t s2u(const void* p) {
    return (uint32_t)__cvta_generic_to_shared(p);
}
__device__ __forceinline__ void cp16(uint32_t dst, const void* src) {
    asm volatile("cp.async.ca.shared.global [%0], [%1], 16;" :: "r"(dst), "l"(src));
}
#define CP_COMMIT() asm volatile("cp.async.commit_group;")
#define CP_WAIT1()  asm volatile("cp.async.wait_group 1;")
#define CP_WAIT0()  asm volatile("cp.async.wait_group 0;")

__device__ __forceinline__ void ldsm4(uint32_t* r, uint32_t addr) {
    asm volatile("ldmatrix.sync.aligned.m8n8.x4.shared.b16 {%0,%1,%2,%3}, [%4];"
        : "=r"(r[0]), "=r"(r[1]), "=r"(r[2]), "=r"(r[3]) : "r"(addr));
}
__device__ __forceinline__ void ldsm4t(uint32_t* r, uint32_t addr) {
    asm volatile("ldmatrix.sync.aligned.m8n8.x4.trans.shared.b16 {%0,%1,%2,%3}, [%4];"
        : "=r"(r[0]), "=r"(r[1]), "=r"(r[2]), "=r"(r[3]) : "r"(addr));
}
__device__ __forceinline__ void mma_f16(float* c, const uint32_t* a, const uint32_t* b) {
    asm volatile(
        "mma.sync.aligned.m16n8k16.row.col.f32.f16.f16.f32 "
        "{%0,%1,%2,%3}, {%4,%5,%6,%7}, {%8,%9}, {%0,%1,%2,%3};"
        : "+f"(c[0]), "+f"(c[1]), "+f"(c[2]), "+f"(c[3])
        : "r"(a[0]), "r"(a[1]), "r"(a[2]), "r"(a[3]), "r"(b[0]), "r"(b[1]));
}

__device__ __forceinline__ uint32_t pk2h(__half a, __half b) {
    return (uint32_t)__half_as_ushort(a) | ((uint32_t)__half_as_ushort(b) << 16);
}

// ---------------- init ----------------
__global__ void zero_kernel() {
    int i = blockIdx.x * blockDim.x + threadIdx.x;
    if (i < NPAD) g_ltok[i] = -1;
    if (i < E_EXP) { g_count[i] = 0; g_smsum[i] = 0.0f; g_cursor[i] = 0; }
}

// ---------------- weight convert: fp32 -> fp16 ----------------
// tensor index = blockIdx.y + ysel: 0 -> w1, 1 -> w2, 2 -> wp
__global__ void convW_kernel(const float4* __restrict__ w1,
                             const float4* __restrict__ w2,
                             const float4* __restrict__ wp, int ysel, int n4) {
    int i = blockIdx.x * blockDim.x + threadIdx.x;
    if (i >= n4) return;
    int which = blockIdx.y + ysel;
    const float4* src;
    uint2* dst;
    if (which == 0)      { src = w1; dst = (uint2*)g_w1h; }
    else if (which == 1) { src = w2; dst = (uint2*)g_w2h; }
    else                 { src = wp; dst = (uint2*)g_wph; }
    float4 v = src[i];
    uint2 o;
    o.x = pk2h(__float2half_rn(v.x), __float2half_rn(v.y));
    o.y = pk2h(__float2half_rn(v.z), __float2half_rn(v.w));
    dst[i] = o;
}

// ---------------- gating ----------------
__global__ void gate_kernel(const float* __restrict__ x,
                            const float* __restrict__ noise,
                            const float* __restrict__ gw,
                            const float* __restrict__ nw,
                            float* __restrict__ out) {
    int t = blockIdx.x;
    int w = threadIdx.x >> 5;
    int lane = threadIdx.x & 31;
    __shared__ float logit[E_EXP];

    const float* xr = x + (size_t)t * D_DIM;
    float s = 0.0f;
    for (int d = lane; d < D_DIM; d += 32)
        s += xr[d] * gw[d * E_EXP + w];
    #pragma unroll
    for (int o = 16; o; o >>= 1) s += __shfl_xor_sync(0xffffffffu, s, o);
    if (lane == 0) logit[w] = s;
    __syncthreads();

    if (threadIdx.x == 0) {
        float l[E_EXP], ln[E_EXP];
        float m = -1e30f;
        #pragma unroll
        for (int e = 0; e < E_EXP; e++) { l[e] = logit[e]; m = fmaxf(m, l[e]); }
        float sum = 0.0f;
        float ex[E_EXP];
        #pragma unroll
        for (int e = 0; e < E_EXP; e++) { ex[e] = expf(l[e] - m); sum += ex[e]; }
        float inv = 1.0f / sum;
        #pragma unroll
        for (int e = 0; e < E_EXP; e++) atomicAdd(&g_smsum[e], ex[e] * inv);

        #pragma unroll
        for (int e = 0; e < E_EXP; e++) ln[e] = l[e] + noise[t * E_EXP + e] * nw[e];

        int b0 = 0;
        #pragma unroll
        for (int e = 1; e < E_EXP; e++) if (ln[e] > ln[b0]) b0 = e;
        int b1 = (b0 == 0) ? 1 : 0;
        #pragma unroll
        for (int e = 0; e < E_EXP; e++) if (e != b0 && ln[e] > ln[b1]) b1 = e;

        float v0 = ln[b0], v1 = ln[b1];
        float mm = fmaxf(v0, v1);
        float e0 = expf(v0 - mm), e1 = expf(v1 - mm);
        float denom = 1.0f / (e0 + e1);

        g_e[t][0] = b0; g_e[t][1] = b1;
        g_g[t][0] = e0 * denom; g_g[t][1] = e1 * denom;
        atomicAdd(&g_count[b0], 1);
        atomicAdd(&g_count[b1], 1);
        out[OUT_IDS + t * K_TOP + 0] = (float)b0;
        out[OUT_IDS + t * K_TOP + 1] = (float)b1;
    }
}

// ---------------- padded offsets + lb loss ----------------
__global__ void offsets_kernel(float* __restrict__ out) {
    if (threadIdx.x == 0) {
        int acc = 0;
        #pragma unroll
        for (int e = 0; e < E_EXP; e++) {
            g_offset[e] = acc;
            acc += (g_count[e] + 127) & ~127;
        }
        g_offset[E_EXP] = acc;
        float loss = 0.0f;
        #pragma unroll
        for (int e = 0; e < E_EXP; e++) {
            float gm = g_smsum[e] / (float)T_TOK - 1.0f / (float)E_EXP;
            loss += gm * gm;
        }
        out[OUT_LOSS] = (loss / (float)E_EXP) * 0.01f;
    }
}

// ---------------- scatter ----------------
__global__ void scatter_kernel() {
    int t = blockIdx.x * blockDim.x + threadIdx.x;
    if (t >= T_TOK) return;
    #pragma unroll
    for (int k = 0; k < K_TOP; k++) {
        int e = g_e[t][k];
        int pos = atomicAdd(&g_cursor[e], 1);
        int r = g_offset[e] + pos;
        g_ltok[r] = t;
        g_rows[t][k] = r;
    }
}

// ---------------- gather routed x rows -> fp16 ----------------
__global__ void gatherx_kernel(const float* __restrict__ x) {
    int r = blockIdx.x;
    int d = threadIdx.x * 4;
    int t = g_ltok[r];
    uint2 uh = make_uint2(0, 0);
    if (t >= 0) {
        float4 v = *(const float4*)(x + (size_t)t * D_DIM + d);
        uh.x = pk2h(__float2half_rn(v.x), __float2half_rn(v.y));
        uh.y = pk2h(__float2half_rn(v.z), __float2half_rn(v.w));
    }
    *(uint2*)(g_xgh + (size_t)r * D_DIM + d) = uh;
}

// ---------------- HMMA grouped GEMM 1: act = (x@w1+b1)*silu(x@w2+b2) ----------------
__global__ __launch_bounds__(256) void gemm1_mma(
        const float* __restrict__ b1, const float* __restrict__ b2) {
    int e = blockIdx.z;
    int cnt = g_count[e];
    int m0 = blockIdx.x * 128;
    if (m0 >= cnt) return;
    int rbase = g_offset[e] + m0;
    int hb = blockIdx.y * 64;
    int tid = threadIdx.x;
    int lane = tid & 31, wid = tid >> 5;
    int wm = (wid & 3) * 32, wn = (wid >> 2) * 32;

    extern __shared__ char smraw[];
    __half* smb = (__half*)smraw;
    const int A_SZ = 128 * 40;
    const int B_SZ = 32 * 72;
    const int STG  = A_SZ + 2 * B_SZ;
    const uint32_t STGB = (uint32_t)STG * 2;

    int a_row = tid >> 1, a_half = tid & 1;
    int b_row = tid >> 3, b_col = (tid & 7) * 8;

    const __half* xh_p = g_xgh + (size_t)(rbase + a_row) * D_DIM + a_half * 16;
    const __half* w1_p = g_w1h + (size_t)e * D_DIM * H_DIM + hb + b_col;
    const __half* w2_p = g_w2h + (size_t)e * D_DIM * H_DIM + hb + b_col;

    uint32_t smbase = s2u(smb);
    uint32_t dAh = smbase + (uint32_t)(a_row * 40 + a_half * 16) * 2;
    uint32_t dB1 = smbase + (uint32_t)(A_SZ + b_row * 72 + b_col) * 2;
    uint32_t dB2 = dB1 + B_SZ * 2;

    float accH[2][4][4], accG[2][4][4];
    #pragma unroll
    for (int i = 0; i < 2; i++)
        #pragma unroll
        for (int j = 0; j < 4; j++)
            #pragma unroll
            for (int k = 0; k < 4; k++) { accH[i][j][k] = 0.f; accG[i][j][k] = 0.f; }

    const int NK = D_DIM / 32;   // 24

    {
        cp16(dAh, xh_p);  cp16(dAh + 16, xh_p + 8);
        size_t rk = (size_t)b_row * H_DIM;
        cp16(dB1, w1_p + rk);
        cp16(dB2, w2_p + rk);
        CP_COMMIT();
    }

    for (int kc = 0; kc < NK; kc++) {
        int p = kc & 1;
        if (kc + 1 < NK) {
            int k0 = (kc + 1) * 32;
            uint32_t so = (uint32_t)((kc + 1) & 1) * STGB;
            cp16(dAh + so, xh_p + k0);  cp16(dAh + so + 16, xh_p + k0 + 8);
            size_t rk = (size_t)(k0 + b_row) * H_DIM;
            cp16(dB1 + so, w1_p + rk);
            cp16(dB2 + so, w2_p + rk);
            CP_COMMIT();
            CP_WAIT1();
        } else {
            CP_WAIT0();
        }
        __syncthreads();

        __half* sAh = smb + p * STG;
        __half* sB1 = sAh + A_SZ;
        __half* sB2 = sB1 + B_SZ;

        #pragma unroll
        for (int k16 = 0; k16 < 32; k16 += 16) {
            uint32_t ah[2][4];
            #pragma unroll
            for (int mt = 0; mt < 2; mt++) {
                int ro = wm + mt * 16 + (lane & 15);
                int co = k16 + ((lane >> 4) << 3);
                ldsm4(ah[mt], s2u(sAh + ro * 40 + co));
            }
            #pragma unroll
            for (int q = 0; q < 2; q++) {
                int ro = k16 + (lane & 15);
                int co = wn + q * 16 + ((lane >> 4) << 3);
                uint32_t rb1[4], rb2[4];
                ldsm4t(rb1, s2u(sB1 + ro * 72 + co));
                ldsm4t(rb2, s2u(sB2 + ro * 72 + co));
                #pragma unroll
                for (int mt = 0; mt < 2; mt++)
                    #pragma unroll
                    for (int j = 0; j < 2; j++) {
                        mma_f16(accH[mt][q * 2 + j], ah[mt], &rb1[j * 2]);
                        mma_f16(accG[mt][q * 2 + j], ah[mt], &rb2[j * 2]);
                    }
            }
        }
        __syncthreads();
    }

    const float* b1p = b1 + (size_t)e * H_DIM + hb;
    const float* b2p = b2 + (size_t)e * H_DIM + hb;
    #pragma unroll
    for (int mt = 0; mt < 2; mt++) {
        int row0 = rbase + wm + mt * 16 + (lane >> 2);
        #pragma unroll
        for (int nt = 0; nt < 4; nt++) {
            int cl = wn + nt * 8 + (lane & 3) * 2;
            float bb1a = b1p[cl], bb1b = b1p[cl + 1];
            float bb2a = b2p[cl], bb2b = b2p[cl + 1];
            #pragma unroll
            for (int hf = 0; hf < 2; hf++) {
                float hv0 = accH[mt][nt][hf * 2 + 0] + bb1a;
                float hv1 = accH[mt][nt][hf * 2 + 1] + bb1b;
                float gv0 = accG[mt][nt][hf * 2 + 0] + bb2a;
                float gv1 = accG[mt][nt][hf * 2 + 1] + bb2b;
                float a0 = hv0 * (gv0 / (1.0f + expf(-gv0)));
                float a1 = hv1 * (gv1 / (1.0f + expf(-gv1)));
                uint32_t vh = pk2h(__float2half_rn(a0), __float2half_rn(a1));
                size_t off = (size_t)(row0 + hf * 8) * H_DIM + hb + cl;
                *(uint32_t*)(g_acth + off) = vh;
            }
        }
    }
}

// ---------------- HMMA grouped GEMM 2: y = act @ wp + bp ----------------
__global__ __launch_bounds__(256) void gemm2_mma(const float* __restrict__ bp) {
    int e = blockIdx.z;
    int cnt = g_count[e];
    int m0 = blockIdx.x * 128;
    if (m0 >= cnt) return;
    int rbase = g_offset[e] + m0;
    int db = blockIdx.y * 128;
    int tid = threadIdx.x;
    int lane = tid & 31, wid = tid >> 5;
    int wm = (wid & 3) * 32, wn = (wid >> 2) * 64;

    extern __shared__ char smraw[];
    __half* smb = (__half*)smraw;
    const int A_SZ = 128 * 40;
    const int B_SZ = 32 * 136;
    const int STG  = A_SZ + B_SZ;
    const uint32_t STGB = (uint32_t)STG * 2;

    int a_row = tid >> 1, a_half = tid & 1;
    int b_row = tid >> 3, b_col = (tid & 7) * 16;

    const __half* ah_p = g_acth + (size_t)(rbase + a_row) * H_DIM + a_half * 16;
    const __half* wp_p = g_wph + (size_t)e * H_DIM * D_DIM + db + b_col;

    uint32_t smbase = s2u(smb);
    uint32_t dAh = smbase + (uint32_t)(a_row * 40 + a_half * 16) * 2;
    uint32_t dB  = smbase + (uint32_t)(A_SZ + b_row * 136 + b_col) * 2;

    float acc[2][8][4];
    #pragma unroll
    for (int i = 0; i < 2; i++)
        #pragma unroll
        for (int j = 0; j < 8; j++)
            #pragma unroll
            for (int k = 0; k < 4; k++) acc[i][j][k] = 0.f;

    const int NK = H_DIM / 32;   // 96

    {
        cp16(dAh, ah_p);  cp16(dAh + 16, ah_p + 8);
        size_t rk = (size_t)b_row * D_DIM;
        cp16(dB, wp_p + rk);  cp16(dB + 16, wp_p + rk + 8);
        CP_COMMIT();
    }

    for (int kc = 0; kc < NK; kc++) {
        int p = kc & 1;
        if (kc + 1 < NK) {
            int k0 = (kc + 1) * 32;
            uint32_t so = (uint32_t)((kc + 1) & 1) * STGB;
            cp16(dAh + so, ah_p + k0);  cp16(dAh + so + 16, ah_p + k0 + 8);
            size_t rk = (size_t)(k0 + b_row) * D_DIM;
            cp16(dB + so, wp_p + rk);  cp16(dB + so + 16, wp_p + rk + 8);
            CP_COMMIT();
            CP_WAIT1();
        } else {
            CP_WAIT0();
        }
        __syncthreads();

        __half* sAh = smb + p * STG;
        __half* sB  = sAh + A_SZ;

        #pragma unroll
        for (int k16 = 0; k16 < 32; k16 += 16) {
            uint32_t ah[2][4];
            #pragma unroll
            for (int mt = 0; mt < 2; mt++) {
                int ro = wm + mt * 16 + (lane & 15);
                int co = k16 + ((lane >> 4) << 3);
                ldsm4(ah[mt], s2u(sAh + ro * 40 + co));
            }
            #pragma unroll
            for (int q = 0; q < 4; q++) {
                int ro = k16 + (lane & 15);
                int co = wn + q * 16 + ((lane >> 4) << 3);
                uint32_t rb[4];
                ldsm4t(rb, s2u(sB + ro * 136 + co));
                #pragma unroll
                for (int mt = 0; mt < 2; mt++)
                    #pragma unroll
                    for (int j = 0; j < 2; j++)
                        mma_f16(acc[mt][q * 2 + j], ah[mt], &rb[j * 2]);
            }
        }
        __syncthreads();
    }

    const float* bpp = bp + (size_t)e * D_DIM + db;
    #pragma unroll
    for (int mt = 0; mt < 2; mt++) {
        int row0 = rbase + wm + mt * 16 + (lane >> 2);
        #pragma unroll
        for (int nt = 0; nt < 8; nt++) {
            int cl = wn + nt * 8 + (lane & 3) * 2;
            float ba = bpp[cl], bb = bpp[cl + 1];
            #pragma unroll
            for (int hf = 0; hf < 2; hf++) {
                float2 v;
                v.x = acc[mt][nt][hf * 2 + 0] + ba;
                v.y = acc[mt][nt][hf * 2 + 1] + bb;
                *(float2*)(g_y + (size_t)(row0 + hf * 8) * D_DIM + db + cl) = v;
            }
        }
    }
}

// ---------------- final combine: out[t] = g0*y[r0] + g1*y[r1] ----------------
__global__ void combine_kernel(float* __restrict__ out) {
    int t = blockIdx.x;
    int d = threadIdx.x * 4;
    int r0 = g_rows[t][0], r1 = g_rows[t][1];
    float g0 = g_g[t][0], g1 = g_g[t][1];
    float4 a = *(const float4*)(g_y + (size_t)r0 * D_DIM + d);
    float4 b = *(const float4*)(g_y + (size_t)r1 * D_DIM + d);
    float4 o;
    o.x = g0 * a.x + g1 * b.x;
    o.y = g0 * a.y + g1 * b.y;
    o.z = g0 * a.z + g1 * b.z;
    o.w = g0 * a.w + g1 * b.w;
    *(float4*)(out + (size_t)t * D_DIM + d) = o;
}

// ---------------- launch ----------------
extern "C" void kernel_launch(void* const* d_in, const int* in_sizes, int n_in,
                              void* d_out, int out_size) {
    const float* x     = (const float*)d_in[0];
    const float* noise = (const float*)d_in[1];
    const float* gw    = (const float*)d_in[2];
    const float* nw    = (const float*)d_in[3];
    const float* w1    = (const float*)d_in[4];
    const float* b1    = (const float*)d_in[5];
    const float* w2    = (const float*)d_in[6];
    const float* b2    = (const float*)d_in[7];
    const float* wp    = (const float*)d_in[8];
    const float* bp    = (const float*)d_in[9];
    float* out = (float*)d_out;

    const int SM1 = 2 * (128 * 40 + 2 * 32 * 72) * 2;   // 38912 B
    const int SM2 = 2 * (128 * 40 + 32 * 136) * 2;      // 37888 B
    cudaFuncSetAttribute(gemm1_mma, cudaFuncAttributeMaxDynamicSharedMemorySize, SM1);
    cudaFuncSetAttribute(gemm2_mma, cudaFuncAttributeMaxDynamicSharedMemorySize, SM2);

    // side stream + events, created once (first call is the non-captured
    // correctness run; creation never happens inside graph capture)
    static cudaStream_t s2 = nullptr;
    static cudaEvent_t evFork = nullptr, evW12 = nullptr, evWp = nullptr;
    if (s2 == nullptr) {
        cudaStreamCreateWithFlags(&s2, cudaStreamNonBlocking);
        cudaEventCreateWithFlags(&evFork, cudaEventDisableTiming);
        cudaEventCreateWithFlags(&evW12, cudaEventDisableTiming);
        cudaEventCreateWithFlags(&evWp, cudaEventDisableTiming);
    }

    const int NW4 = E_EXP * D_DIM * H_DIM / 4;

    // fork: convW runs on s2 concurrently with the gating/scatter chain
    cudaEventRecord(evFork, 0);
    cudaStreamWaitEvent(s2, evFork, 0);
    convW_kernel<<<dim3((NW4 + 255) / 256, 2), 256, 0, s2>>>(
        (const float4*)w1, (const float4*)w2, (const float4*)wp, 0, NW4);
    cudaEventRecord(evW12, s2);
    convW_kernel<<<dim3((NW4 + 255) / 256, 1), 256, 0, s2>>>(
        (const float4*)w1, (const float4*)w2, (const float4*)wp, 2, NW4);
    cudaEventRecord(evWp, s2);

    // main stream: prologue chain
    zero_kernel<<<(NPAD + 255) / 256, 256>>>();
    gate_kernel<<<T_TOK, 256>>>(x, noise, gw, nw, out);
    offsets_kernel<<<1, 32>>>(out);
    scatter_kernel<<<(T_TOK + 255) / 256, 256>>>();
    gatherx_kernel<<<NPAD, 192>>>(x);

    // join: gemm1 needs w1,w2; gemm2 needs wp
    cudaStreamWaitEvent(0, evW12, 0);
    gemm1_mma<<<dim3(16, H_DIM / 64, E_EXP), 256, SM1>>>(b1, b2);
    cudaStreamWaitEvent(0, evWp, 0);
    gemm2_mma<<<dim3(16, D_DIM / 128, E_EXP), 256, SM2>>>(bp);

    combine_kernel<<<T_TOK, 192>>>(out);
}